// round 4
// baseline (speedup 1.0000x reference)
#include <cuda_runtime.h>
#include <cstdint>

#define NATOMS 25000
#define NPAIRS 500000

__device__ __align__(16) float g_h[NATOMS * 64];
__device__ __align__(16) float g_p[NATOMS * 64];
__device__ __align__(16) float g_newp[NATOMS * 64];

// accurate tanh: 1 - 2/(e^{2x}+1)  (~1e-6 rel err)
__device__ __forceinline__ float tfast(float x) {
    x = fminf(fmaxf(x, -15.f), 15.f);
    float e = __expf(2.f * x);
    return 1.f - __fdividef(2.f, e + 1.f);
}
// split fp32 -> tf32 hi + tf32 lo (3xTF32 scheme)
__device__ __forceinline__ void split(float v, uint32_t& h, uint32_t& l) {
    uint32_t hu; asm("cvt.rna.tf32.f32 %0, %1;" : "=r"(hu) : "f"(v));
    float hf = __uint_as_float(hu);
    asm("cvt.rna.tf32.f32 %0, %1;" : "=r"(l) : "f"(v - hf));
    h = hu;
}

#define MMA_TF32(D, A0, A1, A2, A3, B0, B1) \
    asm volatile("mma.sync.aligned.m16n8k8.row.col.f32.tf32.tf32.f32 " \
        "{%0,%1,%2,%3}, {%4,%5,%6,%7}, {%8,%9}, {%0,%1,%2,%3};" \
        : "+f"((D)[0]), "+f"((D)[1]), "+f"((D)[2]), "+f"((D)[3]) \
        : "r"(A0), "r"(A1), "r"(A2), "r"(A3), "r"(B0), "r"(B1))

// ---------------------------------------------------------------------------
// Weight staging: W (K x N row-major, gmem) -> fragment-ordered float4 smem (fp32).
// frag[((tile*S2 + s2)*32 + lane)] = {W[16s2+tig][c], W[16s2+4+tig][c],
//                                     W[16s2+8+tig][c], W[16s2+12+tig][c]}
// with c = tile*8 + gid.
// ---------------------------------------------------------------------------
__device__ __forceinline__ void stage_frag(const float* __restrict__ W, float4* __restrict__ frag,
                                           int tiles, int s2sh, int N, int tid) {
    const int S2 = 1 << s2sh;
    const int tot = tiles * S2 * 32;
    for (int idx = tid; idx < tot; idx += 256) {
        int lane = idx & 31;
        int rest = idx >> 5;
        int s2 = rest & (S2 - 1);
        int tile = rest >> s2sh;
        int tig = lane & 3, gid = lane >> 2;
        int c = tile * 8 + gid;
        int k0 = s2 * 16 + tig;
        float4 v;
        v.x = W[(k0     ) * N + c];
        v.y = W[(k0 +  4) * N + c];
        v.z = W[(k0 +  8) * N + c];
        v.w = W[(k0 + 12) * N + c];
        frag[idx] = v;
    }
}

// ---------------------------------------------------------------------------
// Warp GEMM (3xTF32): 32 rows x 32 cols (4 tiles from tileBase), K = 16*S2.
// A: XOR-swizzled row-major fp32 smem, (r,k) at (r<<LDSH) + (k ^ ((r&7)<<2)).
// Accumulates hi*hi + hi*lo + lo*hi  (~fp32 accuracy).
// ---------------------------------------------------------------------------
template<int S2, int LDSH>
__device__ __forceinline__ void gemm_tiles3(const float* __restrict__ As,
        const float4* __restrict__ Bf, int r0, int tileBase, int lane, float acc[2][4][4])
{
    const int tig = lane & 3, gid = lane >> 2, swz = gid << 2;
    const float* p0 = As + ((r0 + gid     ) << LDSH);
    const float* p1 = As + ((r0 + gid +  8) << LDSH);
    const float* p2 = As + ((r0 + gid + 16) << LDSH);
    const float* p3 = As + ((r0 + gid + 24) << LDSH);
#pragma unroll
    for (int s2 = 0; s2 < S2; s2++) {
        uint32_t h0[4], l0[4], h1[4], l1[4], h2[4], l2[4], h3[4], l3[4];
#pragma unroll
        for (int m = 0; m < 4; m++) {
            int kk = (16 * s2 + 4 * m + tig) ^ swz;
            split(p0[kk], h0[m], l0[m]);
            split(p1[kk], h1[m], l1[m]);
            split(p2[kk], h2[m], l2[m]);
            split(p3[kk], h3[m], l3[m]);
        }
#pragma unroll
        for (int ct = 0; ct < 4; ct++) {
            float4 b = Bf[((tileBase + ct) * S2 + s2) * 32 + lane];
            uint32_t bxh, bxl, byh, byl, bzh, bzl, bwh, bwl;
            split(b.x, bxh, bxl); split(b.y, byh, byl);
            split(b.z, bzh, bzl); split(b.w, bwh, bwl);
            // rows 0-15 of this 32-row band, k-low (b.x,b.y)
            MMA_TF32(acc[0][ct], h0[0], h1[0], h0[1], h1[1], bxh, byh);
            MMA_TF32(acc[0][ct], h0[0], h1[0], h0[1], h1[1], bxl, byl);
            MMA_TF32(acc[0][ct], l0[0], l1[0], l0[1], l1[1], bxh, byh);
            // rows 0-15, k-high (b.z,b.w)
            MMA_TF32(acc[0][ct], h0[2], h1[2], h0[3], h1[3], bzh, bwh);
            MMA_TF32(acc[0][ct], h0[2], h1[2], h0[3], h1[3], bzl, bwl);
            MMA_TF32(acc[0][ct], l0[2], l1[2], l0[3], l1[3], bzh, bwh);
            // rows 16-31, k-low
            MMA_TF32(acc[1][ct], h2[0], h3[0], h2[1], h3[1], bxh, byh);
            MMA_TF32(acc[1][ct], h2[0], h3[0], h2[1], h3[1], bxl, byl);
            MMA_TF32(acc[1][ct], l2[0], l3[0], l2[1], l3[1], bxh, byh);
            // rows 16-31, k-high
            MMA_TF32(acc[1][ct], h2[2], h3[2], h2[3], h3[3], bzh, bwh);
            MMA_TF32(acc[1][ct], h2[2], h3[2], h2[3], h3[3], bzl, bwl);
            MMA_TF32(acc[1][ct], l2[2], l3[2], l2[3], l3[3], bzh, bwh);
        }
    }
}

// SMEM layout (float offsets), 50112 floats = 200448 B
#define OFF_W1F   0        // 8192  (w1 frags)  -- aliased: BUF0 after stage 1
#define OFF_W2F   8192     // 16384 (w2 frags)
#define OFF_WI1F  24576    // 4096
#define OFF_WI2F  28672    // 4096
#define OFF_PIJ   32768    // 16384 (pij)       -- aliased: BUF1 (first 8192)
#define OFF_BASIS 49152    // 512
#define OFF_B1    49664    // 64
#define OFF_B2    49728    // 256
#define OFF_IDX   49984    // 128 (int)
#define PAIR_SMEM_BYTES (50112 * 4)
#define OFF_BUF0  OFF_W1F
#define OFF_BUF1  OFF_PIJ

__global__ __launch_bounds__(256, 1) void pair_mma(
    const int* __restrict__ ind2, const float* __restrict__ basis,
    const float* __restrict__ w1, const float* __restrict__ b1,
    const float* __restrict__ w2, const float* __restrict__ b2,
    const float* __restrict__ wi1, const float* __restrict__ wi2)
{
    extern __shared__ float sm[];
    const int tid = threadIdx.x;
    const int pairbase = blockIdx.x * 128;

    stage_frag(w1,  (float4*)(sm + OFF_W1F),   8, 3, 64,  tid);  // K=128 -> S2=8
    stage_frag(w2,  (float4*)(sm + OFF_W2F),  32, 2, 256, tid);  // K=64  -> S2=4
    stage_frag(wi1, (float4*)(sm + OFF_WI1F),  8, 2, 64,  tid);
    stage_frag(wi2, (float4*)(sm + OFF_WI2F),  8, 2, 64,  tid);
    if (tid < 64) sm[OFF_B1 + tid] = b1[tid];
    if (tid < 128) {
        sm[OFF_B2 + tid] = b2[tid];
        sm[OFF_B2 + 128 + tid] = b2[128 + tid];
        int p = pairbase + tid;
        if (p < NPAIRS) {
            ((int*)(sm + OFF_IDX))[tid] = ind2[2 * p];
            ((float4*)(sm + OFF_BASIS))[tid] = ((const float4*)basis)[p];
        } else {
            ((int*)(sm + OFF_IDX))[tid] = -1;
            ((float4*)(sm + OFF_BASIS))[tid] = make_float4(0.f, 0.f, 0.f, 0.f);
        }
    }
    // gather pij = [h[i] | h[j]] into swizzled A layout (stride 128)
#pragma unroll
    for (int r = 0; r < 16; r++) {
        int idx = tid + r * 256;
        int p = idx >> 5, seg = idx & 31;
        int gp = pairbase + p;
        float4 v = make_float4(0.f, 0.f, 0.f, 0.f);
        if (gp < NPAIRS) {
            int a = ind2[2 * gp + (seg >> 4)];
            v = ((const float4*)g_h)[a * 16 + (seg & 15)];
        }
        ((float4*)(sm + OFF_PIJ))[p * 32 + (seg ^ (p & 7))] = v;
    }
    __syncthreads();

    const int lane = tid & 31, w = tid >> 5;
    const int rg = w & 3, cg = w >> 2;       // 4 row-groups x 2 col-groups
    const int r0 = rg * 32;
    const int tig = lane & 3, gid = lane >> 2, swz = gid << 2;

    float acc[2][4][4];

    // ---- Stage 1: ww1 = tanh(pij @ w1 + b1), K=128, N=64 ----
    {
#pragma unroll
        for (int i = 0; i < 2; i++)
#pragma unroll
            for (int j = 0; j < 4; j++)
#pragma unroll
                for (int q = 0; q < 4; q++) acc[i][j][q] = 0.f;
        gemm_tiles3<8, 7>(sm + OFF_PIJ, (const float4*)(sm + OFF_W1F), r0, cg * 4, lane, acc);
        __syncthreads();  // everyone done reading w1 frags before BUF0 overwrite
#pragma unroll
        for (int rt = 0; rt < 2; rt++)
#pragma unroll
            for (int ct = 0; ct < 4; ct++) {
                int cc = cg * 32 + ct * 8 + tig * 2;
                int rL = r0 + rt * 16 + gid, rH = rL + 8;
                float2 v;
                v.x = tfast(acc[rt][ct][0] + sm[OFF_B1 + cc]);
                v.y = tfast(acc[rt][ct][1] + sm[OFF_B1 + cc + 1]);
                *(float2*)&sm[OFF_BUF0 + (rL << 6) + (cc ^ swz)] = v;
                v.x = tfast(acc[rt][ct][2] + sm[OFF_B1 + cc]);
                v.y = tfast(acc[rt][ct][3] + sm[OFF_B1 + cc + 1]);
                *(float2*)&sm[OFF_BUF0 + (rH << 6) + (cc ^ swz)] = v;
            }
    }
    __syncthreads();

    // ---- Stage 2: inter = sum_b tanh(ww1 @ w2 + b2) * basis, K=64, N=256 ----
    {
        float4 bsv[4];
#pragma unroll
        for (int q = 0; q < 4; q++) bsv[q] = ((float4*)(sm + OFF_BASIS))[r0 + gid + q * 8];
#pragma unroll
        for (int j = 0; j < 4; j++) {
            int g = cg + 2 * j;   // col group 0..7 (32 cols each)
#pragma unroll
            for (int i = 0; i < 2; i++)
#pragma unroll
                for (int jj = 0; jj < 4; jj++)
#pragma unroll
                    for (int q = 0; q < 4; q++) acc[i][jj][q] = 0.f;
            gemm_tiles3<4, 6>(sm + OFF_BUF0, (const float4*)(sm + OFF_W2F), r0, g * 4, lane, acc);
#pragma unroll
            for (int rt = 0; rt < 2; rt++)
#pragma unroll
                for (int ct = 0; ct < 4; ct++) {
                    int col0 = g * 32 + ct * 8 + tig * 2;
                    float b20 = sm[OFF_B2 + col0], b21 = sm[OFF_B2 + col0 + 1];
                    float4 bL = bsv[rt * 2 + 0], bH = bsv[rt * 2 + 1];
                    float cL0 = (tig & 1) ? bL.z : bL.x, cL1 = (tig & 1) ? bL.w : bL.y;
                    float cH0 = (tig & 1) ? bH.z : bH.x, cH1 = (tig & 1) ? bH.w : bH.y;
                    float pl = tfast(acc[rt][ct][0] + b20) * cL0 + tfast(acc[rt][ct][1] + b21) * cL1;
                    float ph = tfast(acc[rt][ct][2] + b20) * cH0 + tfast(acc[rt][ct][3] + b21) * cH1;
                    pl += __shfl_xor_sync(0xffffffffu, pl, 1);
                    ph += __shfl_xor_sync(0xffffffffu, ph, 1);
                    if ((tig & 1) == 0) {
                        int ci = g * 8 + ct * 2 + (tig >> 1);
                        int rL = r0 + rt * 16 + gid, rH = rL + 8;
                        sm[OFF_BUF1 + (rL << 6) + (ci ^ swz)] = pl;
                        sm[OFF_BUF1 + (rH << 6) + (ci ^ swz)] = ph;
                    }
                }
        }
    }
    __syncthreads();

    // ---- Stage 3: t1 = tanh(inter @ ii_w1), K=64, N=64 ----
    {
#pragma unroll
        for (int i = 0; i < 2; i++)
#pragma unroll
            for (int j = 0; j < 4; j++)
#pragma unroll
                for (int q = 0; q < 4; q++) acc[i][j][q] = 0.f;
        gemm_tiles3<4, 6>(sm + OFF_BUF1, (const float4*)(sm + OFF_WI1F), r0, cg * 4, lane, acc);
#pragma unroll
        for (int rt = 0; rt < 2; rt++)
#pragma unroll
            for (int ct = 0; ct < 4; ct++) {
                int cc = cg * 32 + ct * 8 + tig * 2;
                int rL = r0 + rt * 16 + gid, rH = rL + 8;
                float2 v;
                v.x = tfast(acc[rt][ct][0]);
                v.y = tfast(acc[rt][ct][1]);
                *(float2*)&sm[OFF_BUF0 + (rL << 6) + (cc ^ swz)] = v;
                v.x = tfast(acc[rt][ct][2]);
                v.y = tfast(acc[rt][ct][3]);
                *(float2*)&sm[OFF_BUF0 + (rH << 6) + (cc ^ swz)] = v;
            }
    }
    __syncthreads();

    // ---- Stage 4: t2 = tanh(t1 @ ii_w2); scatter into g_newp[ind_i] ----
    {
#pragma unroll
        for (int i = 0; i < 2; i++)
#pragma unroll
            for (int j = 0; j < 4; j++)
#pragma unroll
                for (int q = 0; q < 4; q++) acc[i][j][q] = 0.f;
        gemm_tiles3<4, 6>(sm + OFF_BUF0, (const float4*)(sm + OFF_WI2F), r0, cg * 4, lane, acc);
        const int* idxS = (const int*)(sm + OFF_IDX);
#pragma unroll
        for (int rt = 0; rt < 2; rt++)
#pragma unroll
            for (int ct = 0; ct < 4; ct++) {
                int cc = cg * 32 + ct * 8 + tig * 2;
                int rL = r0 + rt * 16 + gid, rH = rL + 8;
                int aL = idxS[rL], aH = idxS[rH];
                if (aL >= 0) {
                    atomicAdd(&g_newp[aL * 64 + cc    ], tfast(acc[rt][ct][0]));
                    atomicAdd(&g_newp[aL * 64 + cc + 1], tfast(acc[rt][ct][1]));
                }
                if (aH >= 0) {
                    atomicAdd(&g_newp[aH * 64 + cc    ], tfast(acc[rt][ct][2]));
                    atomicAdd(&g_newp[aH * 64 + cc + 1], tfast(acc[rt][ct][3]));
                }
            }
    }
}

// ---------------------------------------------------------------------------
// fp32 4x4 register-tile helper for atom kernels
// ---------------------------------------------------------------------------
__device__ __forceinline__ void mm4(float acc[4][4], const float* __restrict__ A, int lda,
                                    const float* __restrict__ W, int ldw, int k4) {
    float4 w0 = *(const float4*)(W + (k4 * 4 + 0) * ldw);
    float4 w1 = *(const float4*)(W + (k4 * 4 + 1) * ldw);
    float4 w2 = *(const float4*)(W + (k4 * 4 + 2) * ldw);
    float4 w3 = *(const float4*)(W + (k4 * 4 + 3) * ldw);
#pragma unroll
    for (int i = 0; i < 4; i++) {
        float4 a = *(const float4*)(A + i * lda + k4 * 4);
        acc[i][0] = fmaf(a.x, w0.x, fmaf(a.y, w1.x, fmaf(a.z, w2.x, fmaf(a.w, w3.x, acc[i][0]))));
        acc[i][1] = fmaf(a.x, w0.y, fmaf(a.y, w1.y, fmaf(a.z, w2.y, fmaf(a.w, w3.y, acc[i][1]))));
        acc[i][2] = fmaf(a.x, w0.z, fmaf(a.y, w1.z, fmaf(a.z, w2.z, fmaf(a.w, w3.z, acc[i][2]))));
        acc[i][3] = fmaf(a.x, w0.w, fmaf(a.y, w1.w, fmaf(a.z, w2.w, fmaf(a.w, w3.w, acc[i][3]))));
    }
}

#define PRE_SMEM_BYTES (12352 * 4)
__global__ __launch_bounds__(256, 1) void atom_pre_kernel(
    const float* __restrict__ prop, int d,
    const float* __restrict__ w1, const float* __restrict__ b1,
    const float* __restrict__ w2, const float* __restrict__ b2)
{
    extern __shared__ float sm[];
    float* sSrc = sm;
    float* sW   = sm + 4096;
    float* sH   = sm + 8192;
    float* sB   = sm + 12288;

    const int tid = threadIdx.x;
    const int abase = blockIdx.x * 64;
    const int K0 = (d == 0) ? 16 : 64;
    const int kq = K0 >> 2;
    const float* src = (d == 0) ? prop : g_p;

    for (int i = tid; i < K0 * 64; i += 256) sW[i] = w1[i];
    if (tid < 64) sB[tid] = b1[tid];
    for (int i = tid; i < 64 * kq; i += 256) {
        int a = i / kq, seg = i % kq;
        float4 v = make_float4(0.f, 0.f, 0.f, 0.f);
        if (abase + a < NATOMS) v = ((const float4*)src)[(abase + a) * kq + seg];
        *(float4*)(sSrc + a * 64 + seg * 4) = v;
    }
    for (int i = tid; i < 1024; i += 256) {
        int a = i >> 4;
        if (abase + a < NATOMS)
            ((float4*)g_newp)[(abase + a) * 16 + (i & 15)] = make_float4(0.f, 0.f, 0.f, 0.f);
    }
    __syncthreads();

    const int ar = tid >> 4, cr = tid & 15;
    {
        float acc[4][4];
#pragma unroll
        for (int i = 0; i < 4; i++) { acc[i][0] = acc[i][1] = acc[i][2] = acc[i][3] = 0.f; }
        const float* A = sSrc + ar * 4 * 64;
        const float* W = sW + cr * 4;
        for (int k4 = 0; k4 < kq; k4++) mm4(acc, A, 64, W, 64, k4);
        float4 bv = *(const float4*)(sB + cr * 4);
#pragma unroll
        for (int i = 0; i < 4; i++) {
            float4 v;
            v.x = tfast(acc[i][0] + bv.x); v.y = tfast(acc[i][1] + bv.y);
            v.z = tfast(acc[i][2] + bv.z); v.w = tfast(acc[i][3] + bv.w);
            *(float4*)(sH + (ar * 4 + i) * 64 + cr * 4) = v;
        }
    }
    __syncthreads();
    for (int i = tid; i < 4096; i += 256) sW[i] = w2[i];
    if (tid < 64) sB[tid] = b2[tid];
    __syncthreads();
    {
        float acc[4][4];
#pragma unroll
        for (int i = 0; i < 4; i++) { acc[i][0] = acc[i][1] = acc[i][2] = acc[i][3] = 0.f; }
        const float* A = sH + ar * 4 * 64;
        const float* W = sW + cr * 4;
#pragma unroll 4
        for (int k4 = 0; k4 < 16; k4++) mm4(acc, A, 64, W, 64, k4);
        float4 bv = *(const float4*)(sB + cr * 4);
#pragma unroll
        for (int i = 0; i < 4; i++) {
            int a = abase + ar * 4 + i;
            if (a < NATOMS) {
                float4 v;
                v.x = tfast(acc[i][0] + bv.x); v.y = tfast(acc[i][1] + bv.y);
                v.z = tfast(acc[i][2] + bv.z); v.w = tfast(acc[i][3] + bv.w);
                ((float4*)g_h)[a * 16 + cr] = v;
            }
        }
    }
}

#define POST_SMEM_BYTES (12928 * 4)
__global__ __launch_bounds__(256, 1) void atom_post_kernel(
    const float* __restrict__ prop, const float* __restrict__ res0w,
    const float* __restrict__ w1, const float* __restrict__ b1,
    const float* __restrict__ w2, const float* __restrict__ b2,
    const float* __restrict__ wo, float* __restrict__ out, int d)
{
    extern __shared__ float sm[];
    float* bufA = sm;
    float* bufB = sm + 4352;
    float* sW   = sm + 8704;
    float* sB   = sm + 12800;
    float* sWo  = sm + 12864;

    const int tid = threadIdx.x;
    const int abase = blockIdx.x * 64;
    const int ar = tid >> 4, cr = tid & 15;

    float pn[4][4];
#pragma unroll
    for (int i = 0; i < 4; i++) { pn[i][0] = pn[i][1] = pn[i][2] = pn[i][3] = 0.f; }

    if (d == 0) {
        for (int i = tid; i < 1024; i += 256) sW[i] = res0w[i];
        for (int i = tid; i < 256; i += 256) {
            int a = i >> 2, seg = i & 3;
            float4 v = make_float4(0.f, 0.f, 0.f, 0.f);
            if (abase + a < NATOMS) v = ((const float4*)prop)[(abase + a) * 4 + seg];
            *(float4*)(bufB + a * 16 + seg * 4) = v;
        }
        __syncthreads();
        const float* A = bufB + ar * 4 * 16;
        const float* W = sW + cr * 4;
#pragma unroll
        for (int k4 = 0; k4 < 4; k4++) mm4(pn, A, 16, W, 64, k4);
    }

#pragma unroll
    for (int i = 0; i < 4; i++) {
        int a = abase + ar * 4 + i;
        float4 v = make_float4(0.f, 0.f, 0.f, 0.f);
        if (a < NATOMS) {
            float4 np = ((const float4*)g_newp)[a * 16 + cr];
            if (d == 0) {
                v.x = pn[i][0] + np.x; v.y = pn[i][1] + np.y;
                v.z = pn[i][2] + np.z; v.w = pn[i][3] + np.w;
            } else {
                float4 pv = ((const float4*)g_p)[a * 16 + cr];
                v.x = pv.x + np.x; v.y = pv.y + np.y;
                v.z = pv.z + np.z; v.w = pv.w + np.w;
            }
            ((float4*)g_p)[a * 16 + cr] = v;
        }
        *(float4*)(bufA + (ar * 4 + i) * 68 + cr * 4) = v;
    }
    __syncthreads();

    for (int i = tid; i < 4096; i += 256) sW[i] = w1[i];
    if (tid < 64) { sB[tid] = b1[tid]; sWo[tid] = wo[tid]; }
    __syncthreads();

    {
        float acc[4][4];
#pragma unroll
        for (int i = 0; i < 4; i++) { acc[i][0] = acc[i][1] = acc[i][2] = acc[i][3] = 0.f; }
        const float* A = bufA + ar * 4 * 68;
        const float* W = sW + cr * 4;
#pragma unroll 4
        for (int k4 = 0; k4 < 16; k4++) mm4(acc, A, 68, W, 64, k4);
        float4 bv = *(const float4*)(sB + cr * 4);
#pragma unroll
        for (int i = 0; i < 4; i++) {
            float4 v;
            v.x = tfast(acc[i][0] + bv.x); v.y = tfast(acc[i][1] + bv.y);
            v.z = tfast(acc[i][2] + bv.z); v.w = tfast(acc[i][3] + bv.w);
            *(float4*)(bufB + (ar * 4 + i) * 68 + cr * 4) = v;
        }
    }
    __syncthreads();
    for (int i = tid; i < 4096; i += 256) sW[i] = w2[i];
    if (tid < 64) sB[tid] = b2[tid];
    __syncthreads();

    {
        float acc[4][4];
#pragma unroll
        for (int i = 0; i < 4; i++) { acc[i][0] = acc[i][1] = acc[i][2] = acc[i][3] = 0.f; }
        const float* A = bufB + ar * 4 * 68;
        const float* W = sW + cr * 4;
#pragma unroll 4
        for (int k4 = 0; k4 < 16; k4++) mm4(acc, A, 68, W, 64, k4);
        float4 bv = *(const float4*)(sB + cr * 4);
#pragma unroll
        for (int i = 0; i < 4; i++) {
            float4 v;
            v.x = tfast(acc[i][0] + bv.x); v.y = tfast(acc[i][1] + bv.y);
            v.z = tfast(acc[i][2] + bv.z); v.w = tfast(acc[i][3] + bv.w);
            *(float4*)(bufA + (ar * 4 + i) * 68 + cr * 4) = v;
        }
    }
    __syncthreads();

    if (tid < 64) {
        int a = abase + tid;
        if (a < NATOMS) {
            float s = 0.f;
            const float* row = bufA + tid * 68;
#pragma unroll 8
            for (int c = 0; c < 64; c++) s = fmaf(row[c], sWo[c], s);
            out[a] = (d == 0) ? s : (out[a] + s);
        }
    }
}

// ---------------------------------------------------------------------------
extern "C" void kernel_launch(void* const* d_in, const int* in_sizes, int n_in,
                              void* d_out, int out_size) {
    const int*   ind2   = (const int*)d_in[0];
    const float* prop   = (const float*)d_in[1];
    const float* basis  = (const float*)d_in[2];
    const float* pp0_w1 = (const float*)d_in[3];
    const float* pp0_b1 = (const float*)d_in[4];
    const float* pp_w1  = (const float*)d_in[5];
    const float* pp_b1  = (const float*)d_in[6];
    const float* pp_w2  = (const float*)d_in[7];
    const float* pp_b2  = (const float*)d_in[8];
    const float* pi_w1  = (const float*)d_in[9];
    const float* pi_b1  = (const float*)d_in[10];
    const float* pi_w2  = (const float*)d_in[11];
    const float* pi_b2  = (const float*)d_in[12];
    const float* ii_w1  = (const float*)d_in[13];
    const float* ii_w2  = (const float*)d_in[14];
    const float* res0   = (const float*)d_in[15];
    const float* ow1    = (const float*)d_in[16];
    const float* ob1    = (const float*)d_in[17];
    const float* ow2    = (const float*)d_in[18];
    const float* ob2    = (const float*)d_in[19];
    const float* owo    = (const float*)d_in[20];
    float* out = (float*)d_out;

    static bool inited = false;
    if (!inited) {
        cudaFuncSetAttribute(pair_mma, cudaFuncAttributeMaxDynamicSharedMemorySize, PAIR_SMEM_BYTES);
        cudaFuncSetAttribute(atom_pre_kernel, cudaFuncAttributeMaxDynamicSharedMemorySize, PRE_SMEM_BYTES);
        cudaFuncSetAttribute(atom_post_kernel, cudaFuncAttributeMaxDynamicSharedMemorySize, POST_SMEM_BYTES);
        inited = true;
    }

    const int atom_blocks = (NATOMS + 63) / 64;     // 391
    const int pair_blocks = (NPAIRS + 127) / 128;   // 3907

    for (int d = 0; d < 4; d++) {
        const float* w1 = (d == 0) ? pp0_w1 : pp_w1 + (d - 1) * 4096;
        const float* b1 = (d == 0) ? pp0_b1 : pp_b1 + (d - 1) * 64;
        atom_pre_kernel<<<atom_blocks, 256, PRE_SMEM_BYTES>>>(
            prop, d, w1, b1, pp_w2 + d * 4096, pp_b2 + d * 64);
        pair_mma<<<pair_blocks, 256, PAIR_SMEM_BYTES>>>(
            ind2, basis,
            pi_w1 + d * 8192, pi_b1 + d * 64,
            pi_w2 + d * 16384, pi_b2 + d * 256,
            ii_w1 + d * 4096, ii_w2 + d * 4096);
        atom_post_kernel<<<atom_blocks, 256, POST_SMEM_BYTES>>>(
            prop, res0,
            ow1 + d * 4096, ob1 + d * 64,
            ow2 + d * 4096, ob2 + d * 64,
            owo + d * 64, out, d);
    }
}

// round 5
// speedup vs baseline: 1.3345x; 1.3345x over previous
#include <cuda_runtime.h>
#include <cstdint>

#define NATOMS 25000
#define NPAIRS 500000

typedef unsigned long long ull;

// Scratch (device globals; no allocation allowed)
__device__ __align__(16) float g_h[NATOMS * 64];
__device__ __align__(16) float g_p[NATOMS * 64];
__device__ __align__(16) float g_newp[NATOMS * 64];

// Accurate-enough fast tanh: 1 - 2/(e^{2x}+1), MUFU ex2 + approx divide (~1e-6 rel err)
__device__ __forceinline__ float tfast(float x) {
    x = fminf(fmaxf(x, -15.f), 15.f);
    float e = __expf(2.f * x);
    return 1.f - __fdividef(2.f, e + 1.f);
}

// ---- packed f32x2 helpers (Blackwell FFMA2; ptxas never auto-fuses) ----
__device__ __forceinline__ void ffma2(ull& d, ull a, ull b) {
    asm("fma.rn.f32x2 %0, %1, %2, %0;" : "+l"(d) : "l"(a), "l"(b));
}
__device__ __forceinline__ ull dup2(float x) {
    ull r; asm("mov.b64 %0, {%1, %1};" : "=l"(r) : "f"(x)); return r;
}
__device__ __forceinline__ float2 unp(ull v) {
    float2 f; asm("mov.b64 {%0, %1}, %2;" : "=f"(f.x), "=f"(f.y) : "l"(v)); return f;
}

// 8-row x 4-col register tile over 4 k values, packed: acc[i][0]={c0,c1}, acc[i][1]={c2,c3}
__device__ __forceinline__ void mm8p(ull acc[8][2], const float* __restrict__ A, int lda,
                                     const float* __restrict__ W, int ldw, int k4) {
    const float* w0 = W + (k4 * 4 + 0) * ldw;
    const float* w1 = W + (k4 * 4 + 1) * ldw;
    const float* w2 = W + (k4 * 4 + 2) * ldw;
    const float* w3 = W + (k4 * 4 + 3) * ldw;
    ull w0a = *(const ull*)(w0), w0b = *(const ull*)(w0 + 2);
    ull w1a = *(const ull*)(w1), w1b = *(const ull*)(w1 + 2);
    ull w2a = *(const ull*)(w2), w2b = *(const ull*)(w2 + 2);
    ull w3a = *(const ull*)(w3), w3b = *(const ull*)(w3 + 2);
#pragma unroll
    for (int i = 0; i < 8; i++) {
        float4 a = *(const float4*)(A + i * lda + k4 * 4);
        ull ax = dup2(a.x), ay = dup2(a.y), az = dup2(a.z), aw = dup2(a.w);
        ffma2(acc[i][0], ax, w0a); ffma2(acc[i][1], ax, w0b);
        ffma2(acc[i][0], ay, w1a); ffma2(acc[i][1], ay, w1b);
        ffma2(acc[i][0], az, w2a); ffma2(acc[i][1], az, w2b);
        ffma2(acc[i][0], aw, w3a); ffma2(acc[i][1], aw, w3b);
    }
}

// scalar 4x4 tile for atom kernels (they're ~1% of runtime)
__device__ __forceinline__ void mm4(float acc[4][4], const float* __restrict__ A, int lda,
                                    const float* __restrict__ W, int ldw, int k4) {
    float4 w0 = *(const float4*)(W + (k4 * 4 + 0) * ldw);
    float4 w1 = *(const float4*)(W + (k4 * 4 + 1) * ldw);
    float4 w2 = *(const float4*)(W + (k4 * 4 + 2) * ldw);
    float4 w3 = *(const float4*)(W + (k4 * 4 + 3) * ldw);
#pragma unroll
    for (int i = 0; i < 4; i++) {
        float4 a = *(const float4*)(A + i * lda + k4 * 4);
        acc[i][0] = fmaf(a.x, w0.x, fmaf(a.y, w1.x, fmaf(a.z, w2.x, fmaf(a.w, w3.x, acc[i][0]))));
        acc[i][1] = fmaf(a.x, w0.y, fmaf(a.y, w1.y, fmaf(a.z, w2.y, fmaf(a.w, w3.y, acc[i][1]))));
        acc[i][2] = fmaf(a.x, w0.z, fmaf(a.y, w1.z, fmaf(a.z, w2.z, fmaf(a.w, w3.z, acc[i][2]))));
        acc[i][3] = fmaf(a.x, w0.w, fmaf(a.y, w1.w, fmaf(a.z, w2.w, fmaf(a.w, w3.w, acc[i][3]))));
    }
}

// ---------------------------------------------------------------------------
// Pair kernel: per-depth fused pair pipeline (R1 structure, FFMA2 inner loops).
// 128 pairs per block, 256 threads, ~196KB dynamic smem.
// ---------------------------------------------------------------------------
#define PAIR_SMEM_FLOATS 50112
#define PAIR_SMEM_BYTES  (PAIR_SMEM_FLOATS * 4)

__global__ __launch_bounds__(256, 1) void pair_kernel(
    const int* __restrict__ ind2, const float* __restrict__ basis,
    const float* __restrict__ w1, const float* __restrict__ b1,    // pi_w1[d] 128x64, pi_b1[d] 64
    const float* __restrict__ w2, const float* __restrict__ b2,    // pi_w2[d] 64x256, pi_b2[d] 256
    const float* __restrict__ wi1, const float* __restrict__ wi2)  // ii_w1[d], ii_w2[d] 64x64
{
    extern __shared__ float sm[];
    float* sW2    = sm;             // 16384 (w2 64x256)
    float* sWA    = sm + 16384;     // 8192  (stage1: w1 128x64; stages 3/4: wi1@0, wi2@4096)
    float* sPIJ   = sm + 24576;     // 16384 (stage1 input; then inter=+0, t1=+8192)
    float* sWW1   = sm + 40960;     // 8192
    float* sB1    = sm + 49152;     // 64
    float* sB2    = sm + 49216;     // 256
    float* sBasis = sm + 49472;     // 512
    int*   sIdx   = (int*)(sm + 49984);  // 128

    const int tid = threadIdx.x;
    const int pairbase = blockIdx.x * 128;

    // Stage weights + pair metadata
    for (int i = tid; i < 4096; i += 256) ((float4*)sW2)[i] = ((const float4*)w2)[i];
    for (int i = tid; i < 2048; i += 256) ((float4*)sWA)[i] = ((const float4*)w1)[i];
    if (tid < 64) sB1[tid] = b1[tid];
    if (tid < 128) {
        sB2[tid] = b2[tid];
        sB2[tid + 128] = b2[tid + 128];
        int p = pairbase + tid;
        if (p < NPAIRS) {
            sIdx[tid] = ind2[2 * p];
            ((float4*)sBasis)[tid] = ((const float4*)basis)[p];
        } else {
            sIdx[tid] = -1;
            ((float4*)sBasis)[tid] = make_float4(0.f, 0.f, 0.f, 0.f);
        }
    }
    // Gather pij = [h[i] | h[j]] for 128 pairs (128 floats each = 32 float4)
#pragma unroll
    for (int r = 0; r < 16; r++) {
        int idx = tid + r * 256;         // 0..4095
        int p = idx >> 5, seg = idx & 31;
        int gp = pairbase + p;
        float4 v = make_float4(0.f, 0.f, 0.f, 0.f);
        if (gp < NPAIRS) {
            int atom = ind2[2 * gp + (seg >> 4)];
            v = ((const float4*)g_h)[atom * 16 + (seg & 15)];
        }
        ((float4*)sPIJ)[idx] = v;
    }
    __syncthreads();

    const int pr = tid >> 4, cr = tid & 15;

    // ---- Stage 1: ww1 = tanh(pij @ w1 + b1)  [128x128]@[128x64]
    {
        ull acc[8][2];
#pragma unroll
        for (int i = 0; i < 8; i++) { acc[i][0] = 0ull; acc[i][1] = 0ull; }
        const float* A = sPIJ + pr * 8 * 128;
        const float* W = sWA + cr * 4;
#pragma unroll 4
        for (int k4 = 0; k4 < 32; k4++) mm8p(acc, A, 128, W, 64, k4);
        float4 bv = *(const float4*)(sB1 + cr * 4);
        float* o = sWW1 + pr * 8 * 64 + cr * 4;
#pragma unroll
        for (int i = 0; i < 8; i++) {
            float2 lo = unp(acc[i][0]), hi = unp(acc[i][1]);
            float4 v;
            v.x = tfast(lo.x + bv.x);
            v.y = tfast(lo.y + bv.y);
            v.z = tfast(hi.x + bv.z);
            v.w = tfast(hi.y + bv.w);
            *(float4*)(o + i * 64) = v;
        }
    }
    __syncthreads();

    // Reload sWA with ii weights (w1 dead); completes before next sync
    for (int i = tid; i < 1024; i += 256) ((float4*)sWA)[i] = ((const float4*)wi1)[i];
    for (int i = tid; i < 1024; i += 256) ((float4*)(sWA + 4096))[i] = ((const float4*)wi2)[i];

    // ---- Stage 2: inter[p][c] = sum_b tanh((ww1@w2)[p][c*4+b]+b2) * basis[p][b]
    float* sInter = sPIJ;
    {
        const int c = tid & 63;
        const int pg = tid >> 6;   // 0..3, pairs pg*32..+31
        const float* Wc = sW2 + c * 4;
        const float4 b2v = *(const float4*)(sB2 + c * 4);
#pragma unroll 1
        for (int ch = 0; ch < 4; ch++) {
            const int pb = pg * 32 + ch * 8;
            ull acc[8][2];
#pragma unroll
            for (int i = 0; i < 8; i++) { acc[i][0] = 0ull; acc[i][1] = 0ull; }
            const float* A = sWW1 + pb * 64;
#pragma unroll 4
            for (int k4 = 0; k4 < 16; k4++) mm8p(acc, A, 64, Wc, 256, k4);
#pragma unroll
            for (int i = 0; i < 8; i++) {
                float4 bs = ((const float4*)sBasis)[pb + i];
                float2 lo = unp(acc[i][0]), hi = unp(acc[i][1]);
                float v = tfast(lo.x + b2v.x) * bs.x
                        + tfast(lo.y + b2v.y) * bs.y
                        + tfast(hi.x + b2v.z) * bs.z
                        + tfast(hi.y + b2v.w) * bs.w;
                sInter[(pb + i) * 64 + c] = v;
            }
        }
    }
    __syncthreads();

    // ---- Stage 3: t1 = tanh(inter @ ii_w1)
    float* sT1 = sPIJ + 8192;
    {
        ull acc[8][2];
#pragma unroll
        for (int i = 0; i < 8; i++) { acc[i][0] = 0ull; acc[i][1] = 0ull; }
        const float* A = sInter + pr * 8 * 64;
        const float* W = sWA + cr * 4;
#pragma unroll 4
        for (int k4 = 0; k4 < 16; k4++) mm8p(acc, A, 64, W, 64, k4);
        float* o = sT1 + pr * 8 * 64 + cr * 4;
#pragma unroll
        for (int i = 0; i < 8; i++) {
            float2 lo = unp(acc[i][0]), hi = unp(acc[i][1]);
            float4 v;
            v.x = tfast(lo.x); v.y = tfast(lo.y);
            v.z = tfast(hi.x); v.w = tfast(hi.y);
            *(float4*)(o + i * 64) = v;
        }
    }
    __syncthreads();

    // ---- Stage 4: t2 = tanh(t1 @ ii_w2); atomic scatter into newp[ind_i]
    {
        ull acc[8][2];
#pragma unroll
        for (int i = 0; i < 8; i++) { acc[i][0] = 0ull; acc[i][1] = 0ull; }
        const float* A = sT1 + pr * 8 * 64;
        const float* W = sWA + 4096 + cr * 4;
#pragma unroll 4
        for (int k4 = 0; k4 < 16; k4++) mm8p(acc, A, 64, W, 64, k4);
#pragma unroll
        for (int i = 0; i < 8; i++) {
            int a = sIdx[pr * 8 + i];
            if (a >= 0) {
                float2 lo = unp(acc[i][0]), hi = unp(acc[i][1]);
                float* p = g_newp + a * 64 + cr * 4;
                atomicAdd(p + 0, tfast(lo.x));
                atomicAdd(p + 1, tfast(lo.y));
                atomicAdd(p + 2, tfast(hi.x));
                atomicAdd(p + 3, tfast(hi.y));
            }
        }
    }
}

// ---------------------------------------------------------------------------
// Atom pre-kernel: h = tanh(tanh(p@W1+b1)@W2+b2); also zeroes g_newp.
// ---------------------------------------------------------------------------
#define PRE_SMEM_BYTES (12352 * 4)

__global__ __launch_bounds__(256, 1) void atom_pre_kernel(
    const float* __restrict__ prop, int d,
    const float* __restrict__ w1, const float* __restrict__ b1,
    const float* __restrict__ w2, const float* __restrict__ b2)
{
    extern __shared__ float sm[];
    float* sSrc = sm;           // 64*64 (row stride 64)
    float* sW   = sm + 4096;    // 64*64
    float* sH   = sm + 8192;    // 64*64
    float* sB   = sm + 12288;   // 64

    const int tid = threadIdx.x;
    const int abase = blockIdx.x * 64;
    const int K0 = (d == 0) ? 16 : 64;
    const int kq = K0 >> 2;
    const float* src = (d == 0) ? prop : g_p;

    for (int i = tid; i < K0 * 64; i += 256) sW[i] = w1[i];
    if (tid < 64) sB[tid] = b1[tid];
    for (int i = tid; i < 64 * kq; i += 256) {
        int a = i / kq, seg = i % kq;
        float4 v = make_float4(0.f, 0.f, 0.f, 0.f);
        if (abase + a < NATOMS) v = ((const float4*)src)[(abase + a) * kq + seg];
        *(float4*)(sSrc + a * 64 + seg * 4) = v;
    }
    // zero newp for these atoms (consumed by this depth's pair kernel)
    for (int i = tid; i < 1024; i += 256) {
        int a = i >> 4;
        if (abase + a < NATOMS)
            ((float4*)g_newp)[(abase + a) * 16 + (i & 15)] = make_float4(0.f, 0.f, 0.f, 0.f);
    }
    __syncthreads();

    const int ar = tid >> 4, cr = tid & 15;
    {
        float acc[4][4];
#pragma unroll
        for (int i = 0; i < 4; i++) { acc[i][0] = acc[i][1] = acc[i][2] = acc[i][3] = 0.f; }
        const float* A = sSrc + ar * 4 * 64;
        const float* W = sW + cr * 4;
        for (int k4 = 0; k4 < kq; k4++) mm4(acc, A, 64, W, 64, k4);
        float4 bv = *(const float4*)(sB + cr * 4);
#pragma unroll
        for (int i = 0; i < 4; i++) {
            float4 v;
            v.x = tfast(acc[i][0] + bv.x); v.y = tfast(acc[i][1] + bv.y);
            v.z = tfast(acc[i][2] + bv.z); v.w = tfast(acc[i][3] + bv.w);
            *(float4*)(sH + (ar * 4 + i) * 64 + cr * 4) = v;
        }
    }
    __syncthreads();
    for (int i = tid; i < 4096; i += 256) sW[i] = w2[i];
    if (tid < 64) sB[tid] = b2[tid];
    __syncthreads();
    {
        float acc[4][4];
#pragma unroll
        for (int i = 0; i < 4; i++) { acc[i][0] = acc[i][1] = acc[i][2] = acc[i][3] = 0.f; }
        const float* A = sH + ar * 4 * 64;
        const float* W = sW + cr * 4;
#pragma unroll 4
        for (int k4 = 0; k4 < 16; k4++) mm4(acc, A, 64, W, 64, k4);
        float4 bv = *(const float4*)(sB + cr * 4);
#pragma unroll
        for (int i = 0; i < 4; i++) {
            int a = abase + ar * 4 + i;
            if (a < NATOMS) {
                float4 v;
                v.x = tfast(acc[i][0] + bv.x); v.y = tfast(acc[i][1] + bv.y);
                v.z = tfast(acc[i][2] + bv.z); v.w = tfast(acc[i][3] + bv.w);
                ((float4*)g_h)[a * 16 + cr] = v;
            }
        }
    }
}

// ---------------------------------------------------------------------------
// Atom post-kernel: p update + output head accumulation.
// ---------------------------------------------------------------------------
#define POST_SMEM_BYTES (12928 * 4)

__global__ __launch_bounds__(256, 1) void atom_post_kernel(
    const float* __restrict__ prop, const float* __restrict__ res0w,
    const float* __restrict__ w1, const float* __restrict__ b1,
    const float* __restrict__ w2, const float* __restrict__ b2,
    const float* __restrict__ wo, float* __restrict__ out, int d)
{
    extern __shared__ float sm[];
    float* bufA = sm;            // 64*68 (padded stride 68)
    float* bufB = sm + 4352;     // 64*68
    float* sW   = sm + 8704;     // 4096
    float* sB   = sm + 12800;    // 64
    float* sWo  = sm + 12864;    // 64

    const int tid = threadIdx.x;
    const int abase = blockIdx.x * 64;
    const int ar = tid >> 4, cr = tid & 15;

    float pn[4][4];
#pragma unroll
    for (int i = 0; i < 4; i++) { pn[i][0] = pn[i][1] = pn[i][2] = pn[i][3] = 0.f; }

    if (d == 0) {
        // pn = prop @ res0_w   (K = 16)
        for (int i = tid; i < 1024; i += 256) sW[i] = res0w[i];
        for (int i = tid; i < 256; i += 256) {
            int a = i >> 2, seg = i & 3;
            float4 v = make_float4(0.f, 0.f, 0.f, 0.f);
            if (abase + a < NATOMS) v = ((const float4*)prop)[(abase + a) * 4 + seg];
            *(float4*)(bufB + a * 16 + seg * 4) = v;  // stride 16 (temporary layout)
        }
        __syncthreads();
        const float* A = bufB + ar * 4 * 16;
        const float* W = sW + cr * 4;
#pragma unroll
        for (int k4 = 0; k4 < 4; k4++) mm4(pn, A, 16, W, 64, k4);
    }

    // pnew = (d==0 ? prop@res0 : p) + newp ; write to g_p and bufA
#pragma unroll
    for (int i = 0; i < 4; i++) {
        int a = abase + ar * 4 + i;
        float4 v = make_float4(0.f, 0.f, 0.f, 0.f);
        if (a < NATOMS) {
            float4 np = ((const float4*)g_newp)[a * 16 + cr];
            if (d == 0) {
                v.x = pn[i][0] + np.x; v.y = pn[i][1] + np.y;
                v.z = pn[i][2] + np.z; v.w = pn[i][3] + np.w;
            } else {
                float4 pv = ((const float4*)g_p)[a * 16 + cr];
                v.x = pv.x + np.x; v.y = pv.y + np.y;
                v.z = pv.z + np.z; v.w = pv.w + np.w;
            }
            ((float4*)g_p)[a * 16 + cr] = v;
        }
        *(float4*)(bufA + (ar * 4 + i) * 68 + cr * 4) = v;
    }
    __syncthreads();

    for (int i = tid; i < 4096; i += 256) sW[i] = w1[i];
    if (tid < 64) { sB[tid] = b1[tid]; sWo[tid] = wo[tid]; }
    __syncthreads();

    // o1 = tanh(pnew @ out_w1 + b1) -> bufB (stride 68)
    {
        float acc[4][4];
#pragma unroll
        for (int i = 0; i < 4; i++) { acc[i][0] = acc[i][1] = acc[i][2] = acc[i][3] = 0.f; }
        const float* A = bufA + ar * 4 * 68;
        const float* W = sW + cr * 4;
#pragma unroll 4
        for (int k4 = 0; k4 < 16; k4++) mm4(acc, A, 68, W, 64, k4);
        float4 bv = *(const float4*)(sB + cr * 4);
#pragma unroll
        for (int i = 0; i < 4; i++) {
            float4 v;
            v.x = tfast(acc[i][0] + bv.x); v.y = tfast(acc[i][1] + bv.y);
            v.z = tfast(acc[i][2] + bv.z); v.w = tfast(acc[i][3] + bv.w);
            *(float4*)(bufB + (ar * 4 + i) * 68 + cr * 4) = v;
        }
    }
    __syncthreads();
    for (int i = tid; i < 4096; i += 256) sW[i] = w2[i];
    if (tid < 64) sB[tid] = b2[tid];
    __syncthreads();

    // o2 = tanh(o1 @ out_w2 + b2) -> bufA
    {
        float acc[4][4];
#pragma unroll
        for (int i = 0; i < 4; i++) { acc[i][0] = acc[i][1] = acc[i][2] = acc[i][3] = 0.f; }
        const float* A = bufB + ar * 4 * 68;
        const float* W = sW + cr * 4;
#pragma unroll 4
        for (int k4 = 0; k4 < 16; k4++) mm4(acc, A, 68, W, 64, k4);
        float4 bv = *(const float4*)(sB + cr * 4);
#pragma unroll
        for (int i = 0; i < 4; i++) {
            float4 v;
            v.x = tfast(acc[i][0] + bv.x); v.y = tfast(acc[i][1] + bv.y);
            v.z = tfast(acc[i][2] + bv.z); v.w = tfast(acc[i][3] + bv.w);
            *(float4*)(bufA + (ar * 4 + i) * 68 + cr * 4) = v;
        }
    }
    __syncthreads();

    // output += o2 @ out_wo  (one thread per atom; stride-68 rows avoid conflicts)
    if (tid < 64) {
        int a = abase + tid;
        if (a < NATOMS) {
            float s = 0.f;
            const float* row = bufA + tid * 68;
#pragma unroll 8
            for (int c = 0; c < 64; c++) s = fmaf(row[c], sWo[c], s);
            out[a] = (d == 0) ? s : (out[a] + s);
        }
    }
}

// ---------------------------------------------------------------------------
extern "C" void kernel_launch(void* const* d_in, const int* in_sizes, int n_in,
                              void* d_out, int out_size) {
    const int*   ind2   = (const int*)d_in[0];
    const float* prop   = (const float*)d_in[1];
    const float* basis  = (const float*)d_in[2];
    const float* pp0_w1 = (const float*)d_in[3];
    const float* pp0_b1 = (const float*)d_in[4];
    const float* pp_w1  = (const float*)d_in[5];
    const float* pp_b1  = (const float*)d_in[6];
    const float* pp_w2  = (const float*)d_in[7];
    const float* pp_b2  = (const float*)d_in[8];
    const float* pi_w1  = (const float*)d_in[9];
    const float* pi_b1  = (const float*)d_in[10];
    const float* pi_w2  = (const float*)d_in[11];
    const float* pi_b2  = (const float*)d_in[12];
    const float* ii_w1  = (const float*)d_in[13];
    const float* ii_w2  = (const float*)d_in[14];
    const float* res0   = (const float*)d_in[15];
    const float* ow1    = (const float*)d_in[16];
    const float* ob1    = (const float*)d_in[17];
    const float* ow2    = (const float*)d_in[18];
    const float* ob2    = (const float*)d_in[19];
    const float* owo    = (const float*)d_in[20];
    float* out = (float*)d_out;

    static bool inited = false;
    if (!inited) {
        cudaFuncSetAttribute(pair_kernel, cudaFuncAttributeMaxDynamicSharedMemorySize, PAIR_SMEM_BYTES);
        cudaFuncSetAttribute(atom_pre_kernel, cudaFuncAttributeMaxDynamicSharedMemorySize, PRE_SMEM_BYTES);
        cudaFuncSetAttribute(atom_post_kernel, cudaFuncAttributeMaxDynamicSharedMemorySize, POST_SMEM_BYTES);
        inited = true;
    }

    const int atom_blocks = (NATOMS + 63) / 64;     // 391
    const int pair_blocks = (NPAIRS + 127) / 128;   // 3907

    for (int d = 0; d < 4; d++) {
        const float* w1 = (d == 0) ? pp0_w1 : pp_w1 + (d - 1) * 4096;
        const float* b1 = (d == 0) ? pp0_b1 : pp_b1 + (d - 1) * 64;
        atom_pre_kernel<<<atom_blocks, 256, PRE_SMEM_BYTES>>>(
            prop, d, w1, b1, pp_w2 + d * 4096, pp_b2 + d * 64);
        pair_kernel<<<pair_blocks, 256, PAIR_SMEM_BYTES>>>(
            ind2, basis,
            pi_w1 + d * 8192, pi_b1 + d * 64,
            pi_w2 + d * 16384, pi_b2 + d * 256,
            ii_w1 + d * 4096, ii_w2 + d * 4096);
        atom_post_kernel<<<atom_blocks, 256, POST_SMEM_BYTES>>>(
            prop, res0,
            ow1 + d * 4096, ob1 + d * 64,
            ow2 + d * 4096, ob2 + d * 64,
            owo + d * 64, out, d);
    }
}

// round 6
// speedup vs baseline: 2.0074x; 1.5042x over previous
#include <cuda_runtime.h>
#include <cuda_fp16.h>
#include <cstdint>

#define NATOMS 25000
#define NPAIRS 500000

__device__ __align__(16) float g_h[NATOMS * 64];
__device__ __align__(16) float g_p[NATOMS * 64];
__device__ __align__(16) float g_newp[NATOMS * 64];
__device__ __align__(16) float g_u[NATOMS * 64];
__device__ __align__(16) float g_v[NATOMS * 64];

// accurate tanh: 1 - 2/(e^{2x}+1)  (~1e-6 rel err)
__device__ __forceinline__ float tfast(float x) {
    x = fminf(fmaxf(x, -15.f), 15.f);
    float e = __expf(2.f * x);
    return 1.f - __fdividef(2.f, e + 1.f);
}

// split two fp32 into packed fp16x2 hi + fp16x2 lo (3xFP16 compensation)
__device__ __forceinline__ void split2(float x0, float x1, uint32_t& H, uint32_t& L) {
    __half h0 = __float2half_rn(x0), h1 = __float2half_rn(x1);
    float r0 = x0 - __half2float(h0);
    float r1 = x1 - __half2float(h1);
    __half2 hh = __halves2half2(h0, h1);
    __half2 ll = __halves2half2(__float2half_rn(r0), __float2half_rn(r1));
    H = *reinterpret_cast<uint32_t*>(&hh);
    L = *reinterpret_cast<uint32_t*>(&ll);
}

__device__ __forceinline__ void mma16(float* d, uint32_t a0, uint32_t a1, uint32_t a2,
                                      uint32_t a3, uint32_t b0, uint32_t b1) {
    asm volatile("mma.sync.aligned.m16n8k16.row.col.f32.f16.f16.f32 "
        "{%0,%1,%2,%3}, {%4,%5,%6,%7}, {%8,%9}, {%0,%1,%2,%3};"
        : "+f"(d[0]), "+f"(d[1]), "+f"(d[2]), "+f"(d[3])
        : "r"(a0), "r"(a1), "r"(a2), "r"(a3), "r"(b0), "r"(b1));
}

// ---------------------------------------------------------------------------
// Weight staging: W (K x N row-major, fp32) -> fp16 hi/lo fragment arrays.
// Per (tile t of 8 cols, kc of 16 ks): 64 u32: [lane*2+0] = b0 = {W[k0][n],W[k0+1][n]},
// [lane*2+1] = b1 = {W[k0+8][n],W[k0+9][n]}, n = t*8+(lane>>2), k0 = kc*16+2*(lane&3).
// ---------------------------------------------------------------------------
__device__ __forceinline__ void stage_w16(const float* __restrict__ W, int N, int tiles,
        uint32_t* __restrict__ H, uint32_t* __restrict__ L, int tid) {
    const int slots = tiles * 4 * 32;
    for (int idx = tid; idx < slots; idx += 256) {
        int lane = idx & 31, kc = (idx >> 5) & 3, t = idx >> 7;
        int n = t * 8 + (lane >> 2);
        int k0 = kc * 16 + 2 * (lane & 3);
        int o = (t * 4 + kc) * 64 + lane * 2;
        uint32_t h, l;
        split2(W[k0 * N + n], W[(k0 + 1) * N + n], h, l);
        H[o] = h; L[o] = l;
        split2(W[(k0 + 8) * N + n], W[(k0 + 9) * N + n], h, l);
        H[o + 1] = h; L[o + 1] = l;
    }
}

// ---------------------------------------------------------------------------
// 3-term fp16 warp GEMM: 32 rows x 32 cols (4 n8-tiles from tileBase), K = 16*KC.
// A: packed fp16x2 hi/lo arrays, word (row, kp) at row*32 + (kp ^ ((row&7)<<2)).
// acc += Ah*Bh + Ah*Bl + Al*Bh.
// ---------------------------------------------------------------------------
template<int KC>
__device__ __forceinline__ void gemm16(const uint32_t* __restrict__ AH, const uint32_t* __restrict__ AL,
        const uint32_t* __restrict__ WH, const uint32_t* __restrict__ WL,
        int r0, int tileBase, int lane, float acc[2][4][4])
{
    const int tig = lane & 3, gid = lane >> 2;
    const int sw = gid << 2;
#pragma unroll
    for (int kc = 0; kc < KC; kc++) {
        int k0 = (kc * 8 + tig) ^ sw;
        int k1 = (kc * 8 + tig + 4) ^ sw;
        uint32_t ah[2][4], al[2][4];
#pragma unroll
        for (int mt = 0; mt < 2; mt++) {
            const uint32_t* bh = AH + (r0 + mt * 16 + gid) * 32;
            const uint32_t* bl = AL + (r0 + mt * 16 + gid) * 32;
            ah[mt][0] = bh[k0]; ah[mt][1] = bh[256 + k0];
            ah[mt][2] = bh[k1]; ah[mt][3] = bh[256 + k1];
            al[mt][0] = bl[k0]; al[mt][1] = bl[256 + k0];
            al[mt][2] = bl[k1]; al[mt][3] = bl[256 + k1];
        }
#pragma unroll
        for (int nt = 0; nt < 4; nt++) {
            int wi = ((tileBase + nt) * KC + kc) * 64 + lane * 2;
            uint2 bh = *(const uint2*)(WH + wi);
            uint2 bl = *(const uint2*)(WL + wi);
#pragma unroll
            for (int mt = 0; mt < 2; mt++) {
                mma16(acc[mt][nt], ah[mt][0], ah[mt][1], ah[mt][2], ah[mt][3], bh.x, bh.y);
                mma16(acc[mt][nt], ah[mt][0], ah[mt][1], ah[mt][2], ah[mt][3], bl.x, bl.y);
                mma16(acc[mt][nt], al[mt][0], al[mt][1], al[mt][2], al[mt][3], bh.x, bh.y);
            }
        }
    }
}

// SMEM layout in u32 words
#define O_WW1H 0        // 4096 (aliased: T1H in stage 3/4)
#define O_WW1L 4096     // 4096 (aliased: T1L)
#define O_INTH 8192     // 4096
#define O_INTL 12288    // 4096
#define O_W2H  16384    // 8192
#define O_W2L  24576    // 8192
#define O_WI1H 32768    // 2048
#define O_WI1L 34816    // 2048
#define O_WI2H 36864    // 2048
#define O_WI2L 38912    // 2048
#define O_BAS  40960    // 512 floats
#define O_B2   41472    // 256 floats
#define O_IDXI 41728    // 128 int
#define O_IDXJ 41856    // 128 int
#define PAIR_SMEM_BYTES (41984 * 4)

__global__ __launch_bounds__(256, 1) void pair_mma(
    const int* __restrict__ ind2, const float* __restrict__ basis,
    const float* __restrict__ w2, const float* __restrict__ b2,
    const float* __restrict__ wi1, const float* __restrict__ wi2)
{
    extern __shared__ uint32_t smw[];
    float* smf = (float*)smw;
    const int tid = threadIdx.x;
    const int pairbase = blockIdx.x * 128;

    stage_w16(w2, 256, 32, smw + O_W2H, smw + O_W2L, tid);
    stage_w16(wi1, 64, 8, smw + O_WI1H, smw + O_WI1L, tid);
    stage_w16(wi2, 64, 8, smw + O_WI2H, smw + O_WI2L, tid);
    if (tid < 128) {
        smf[O_B2 + tid] = b2[tid];
        smf[O_B2 + 128 + tid] = b2[128 + tid];
        int p = pairbase + tid;
        int ai = -1, aj = -1;
        float4 bs = make_float4(0.f, 0.f, 0.f, 0.f);
        if (p < NPAIRS) {
            ai = ind2[2 * p]; aj = ind2[2 * p + 1];
            bs = ((const float4*)basis)[p];
        }
        ((int*)(smw + O_IDXI))[tid] = ai;
        ((int*)(smw + O_IDXJ))[tid] = aj;
        ((float4*)(smf + O_BAS))[tid] = bs;
    }
    // Stage 1: ww1 = tanh(u[i] + v[j])  (b1 folded into u) -> packed hi/lo
#pragma unroll
    for (int r = 0; r < 16; r++) {
        int idx = tid + r * 256;
        int row = idx >> 5, kp = idx & 31;
        int gp = pairbase + row;
        float x0 = 0.f, x1 = 0.f;
        if (gp < NPAIRS) {
            int ai = ind2[2 * gp], aj = ind2[2 * gp + 1];
            float2 u = *(const float2*)&g_u[ai * 64 + 2 * kp];
            float2 v = *(const float2*)&g_v[aj * 64 + 2 * kp];
            x0 = tfast(u.x + v.x);
            x1 = tfast(u.y + v.y);
        }
        uint32_t H, L; split2(x0, x1, H, L);
        int o = row * 32 + (kp ^ ((row & 7) << 2));
        smw[O_WW1H + o] = H; smw[O_WW1L + o] = L;
    }
    __syncthreads();

    const int lane = tid & 31, w = tid >> 5;
    const int rg = w & 3, cg = w >> 2;   // 4 row-groups x 2 col-groups
    const int r0 = rg * 32;
    const int tig = lane & 3, gid = lane >> 2;

    // ---- Stage 2: inter = sum_b tanh(ww1 @ w2 + b2) * basis ----
    {
        float4 bsv[4];
#pragma unroll
        for (int q = 0; q < 4; q++) bsv[q] = ((float4*)(smf + O_BAS))[r0 + gid + q * 8];
#pragma unroll 1
        for (int j = 0; j < 4; j++) {
            int g = cg + 2 * j;
            float acc[2][4][4];
#pragma unroll
            for (int a = 0; a < 2; a++)
#pragma unroll
                for (int b = 0; b < 4; b++)
#pragma unroll
                    for (int q = 0; q < 4; q++) acc[a][b][q] = 0.f;
            gemm16<4>(smw + O_WW1H, smw + O_WW1L, smw + O_W2H, smw + O_W2L, r0, g * 4, lane, acc);
#pragma unroll
            for (int mt = 0; mt < 2; mt++)
#pragma unroll
                for (int nt = 0; nt < 4; nt++) {
                    int c0 = g * 32 + nt * 8 + 2 * tig;
                    float b20 = smf[O_B2 + c0], b21 = smf[O_B2 + c0 + 1];
                    float4 bL = bsv[mt * 2], bH = bsv[mt * 2 + 1];
                    float cL0 = (tig & 1) ? bL.z : bL.x, cL1 = (tig & 1) ? bL.w : bL.y;
                    float cH0 = (tig & 1) ? bH.z : bH.x, cH1 = (tig & 1) ? bH.w : bH.y;
                    float pl = tfast(acc[mt][nt][0] + b20) * cL0 + tfast(acc[mt][nt][1] + b21) * cL1;
                    float ph = tfast(acc[mt][nt][2] + b20) * cH0 + tfast(acc[mt][nt][3] + b21) * cH1;
                    pl += __shfl_xor_sync(0xffffffffu, pl, 1);
                    ph += __shfl_xor_sync(0xffffffffu, ph, 1);
                    float pl2 = __shfl_xor_sync(0xffffffffu, pl, 2);
                    float ph2 = __shfl_xor_sync(0xffffffffu, ph, 2);
                    if (tig == 0) {
                        int kp = g * 4 + nt;
                        int rL = r0 + mt * 16 + gid, rH = rL + 8;
                        uint32_t H, L;
                        split2(pl, pl2, H, L);
                        int o = rL * 32 + (kp ^ (gid << 2));
                        smw[O_INTH + o] = H; smw[O_INTL + o] = L;
                        split2(ph, ph2, H, L);
                        o = rH * 32 + (kp ^ (gid << 2));
                        smw[O_INTH + o] = H; smw[O_INTL + o] = L;
                    }
                }
        }
    }
    __syncthreads();

    // ---- Stage 3: t1 = tanh(inter @ ii_w1) -> packed hi/lo (aliases ww1) ----
    {
        float acc[2][4][4];
#pragma unroll
        for (int a = 0; a < 2; a++)
#pragma unroll
            for (int b = 0; b < 4; b++)
#pragma unroll
                for (int q = 0; q < 4; q++) acc[a][b][q] = 0.f;
        gemm16<4>(smw + O_INTH, smw + O_INTL, smw + O_WI1H, smw + O_WI1L, r0, cg * 4, lane, acc);
#pragma unroll
        for (int mt = 0; mt < 2; mt++)
#pragma unroll
            for (int nt = 0; nt < 4; nt++) {
                int kp = cg * 16 + nt * 4 + tig;
                int rL = r0 + mt * 16 + gid, rH = rL + 8;
                uint32_t H, L;
                split2(tfast(acc[mt][nt][0]), tfast(acc[mt][nt][1]), H, L);
                int o = rL * 32 + (kp ^ (gid << 2));
                smw[O_WW1H + o] = H; smw[O_WW1L + o] = L;
                split2(tfast(acc[mt][nt][2]), tfast(acc[mt][nt][3]), H, L);
                o = rH * 32 + (kp ^ (gid << 2));
                smw[O_WW1H + o] = H; smw[O_WW1L + o] = L;
            }
    }
    __syncthreads();

    // ---- Stage 4: t2 = tanh(t1 @ ii_w2); scatter into g_newp[ind_i] ----
    {
        float acc[2][4][4];
#pragma unroll
        for (int a = 0; a < 2; a++)
#pragma unroll
            for (int b = 0; b < 4; b++)
#pragma unroll
                for (int q = 0; q < 4; q++) acc[a][b][q] = 0.f;
        gemm16<4>(smw + O_WW1H, smw + O_WW1L, smw + O_WI2H, smw + O_WI2L, r0, cg * 4, lane, acc);
        const int* idxI = (const int*)(smw + O_IDXI);
#pragma unroll
        for (int mt = 0; mt < 2; mt++)
#pragma unroll
            for (int nt = 0; nt < 4; nt++) {
                int c0 = cg * 32 + nt * 8 + 2 * tig;
                int rL = r0 + mt * 16 + gid, rH = rL + 8;
                int aL = idxI[rL], aH = idxI[rH];
                if (aL >= 0) {
                    atomicAdd(&g_newp[aL * 64 + c0    ], tfast(acc[mt][nt][0]));
                    atomicAdd(&g_newp[aL * 64 + c0 + 1], tfast(acc[mt][nt][1]));
                }
                if (aH >= 0) {
                    atomicAdd(&g_newp[aH * 64 + c0    ], tfast(acc[mt][nt][2]));
                    atomicAdd(&g_newp[aH * 64 + c0 + 1], tfast(acc[mt][nt][3]));
                }
            }
    }
}

// ---------------------------------------------------------------------------
// fp32 4x4 register-tile helper for atom kernels
// ---------------------------------------------------------------------------
__device__ __forceinline__ void mm4(float acc[4][4], const float* __restrict__ A, int lda,
                                    const float* __restrict__ W, int ldw, int k4) {
    float4 w0 = *(const float4*)(W + (k4 * 4 + 0) * ldw);
    float4 w1 = *(const float4*)(W + (k4 * 4 + 1) * ldw);
    float4 w2 = *(const float4*)(W + (k4 * 4 + 2) * ldw);
    float4 w3 = *(const float4*)(W + (k4 * 4 + 3) * ldw);
#pragma unroll
    for (int i = 0; i < 4; i++) {
        float4 a = *(const float4*)(A + i * lda + k4 * 4);
        acc[i][0] = fmaf(a.x, w0.x, fmaf(a.y, w1.x, fmaf(a.z, w2.x, fmaf(a.w, w3.x, acc[i][0]))));
        acc[i][1] = fmaf(a.x, w0.y, fmaf(a.y, w1.y, fmaf(a.z, w2.y, fmaf(a.w, w3.y, acc[i][1]))));
        acc[i][2] = fmaf(a.x, w0.z, fmaf(a.y, w1.z, fmaf(a.z, w2.z, fmaf(a.w, w3.z, acc[i][2]))));
        acc[i][3] = fmaf(a.x, w0.w, fmaf(a.y, w1.w, fmaf(a.z, w2.w, fmaf(a.w, w3.w, acc[i][3]))));
    }
}

// ---------------------------------------------------------------------------
// Atom pre-kernel: h = tanh(tanh(p@W1+b1)@W2+b2); u = h@piW1_top + pib1;
// v = h@piW1_bot. Also zeroes g_newp.
// ---------------------------------------------------------------------------
#define PRE_SMEM_BYTES (12416 * 4)

__global__ __launch_bounds__(256, 1) void atom_pre_kernel(
    const float* __restrict__ prop, int d,
    const float* __restrict__ w1, const float* __restrict__ b1,
    const float* __restrict__ w2, const float* __restrict__ b2,
    const float* __restrict__ piw1, const float* __restrict__ pib1)
{
    extern __shared__ float sm[];
    float* sSrc = sm;           // 4096 (input p; later h)
    float* sW   = sm + 4096;    // 4096
    float* sH   = sm + 8192;    // 4096
    float* sB   = sm + 12288;   // 64
    float* sB1  = sm + 12352;   // 64

    const int tid = threadIdx.x;
    const int abase = blockIdx.x * 64;
    const int K0 = (d == 0) ? 16 : 64;
    const int kq = K0 >> 2;
    const float* src = (d == 0) ? prop : g_p;

    for (int i = tid; i < K0 * 64; i += 256) sW[i] = w1[i];
    if (tid < 64) { sB[tid] = b1[tid]; sB1[tid] = pib1[tid]; }
    for (int i = tid; i < 64 * kq; i += 256) {
        int a = i / kq, seg = i % kq;
        float4 v = make_float4(0.f, 0.f, 0.f, 0.f);
        if (abase + a < NATOMS) v = ((const float4*)src)[(abase + a) * kq + seg];
        *(float4*)(sSrc + a * 64 + seg * 4) = v;
    }
    for (int i = tid; i < 1024; i += 256) {
        int a = i >> 4;
        if (abase + a < NATOMS)
            ((float4*)g_newp)[(abase + a) * 16 + (i & 15)] = make_float4(0.f, 0.f, 0.f, 0.f);
    }
    __syncthreads();

    const int ar = tid >> 4, cr = tid & 15;
    {
        float acc[4][4];
#pragma unroll
        for (int i = 0; i < 4; i++) { acc[i][0] = acc[i][1] = acc[i][2] = acc[i][3] = 0.f; }
        const float* A = sSrc + ar * 4 * 64;
        const float* W = sW + cr * 4;
        for (int k4 = 0; k4 < kq; k4++) mm4(acc, A, 64, W, 64, k4);
        float4 bv = *(const float4*)(sB + cr * 4);
#pragma unroll
        for (int i = 0; i < 4; i++) {
            float4 v;
            v.x = tfast(acc[i][0] + bv.x); v.y = tfast(acc[i][1] + bv.y);
            v.z = tfast(acc[i][2] + bv.z); v.w = tfast(acc[i][3] + bv.w);
            *(float4*)(sH + (ar * 4 + i) * 64 + cr * 4) = v;
        }
    }
    __syncthreads();
    for (int i = tid; i < 4096; i += 256) sW[i] = w2[i];
    if (tid < 64) sB[tid] = b2[tid];
    __syncthreads();
    {
        float acc[4][4];
#pragma unroll
        for (int i = 0; i < 4; i++) { acc[i][0] = acc[i][1] = acc[i][2] = acc[i][3] = 0.f; }
        const float* A = sH + ar * 4 * 64;
        const float* W = sW + cr * 4;
#pragma unroll 4
        for (int k4 = 0; k4 < 16; k4++) mm4(acc, A, 64, W, 64, k4);
        float4 bv = *(const float4*)(sB + cr * 4);
#pragma unroll
        for (int i = 0; i < 4; i++) {
            int a = abase + ar * 4 + i;
            float4 v;
            v.x = tfast(acc[i][0] + bv.x); v.y = tfast(acc[i][1] + bv.y);
            v.z = tfast(acc[i][2] + bv.z); v.w = tfast(acc[i][3] + bv.w);
            if (a < NATOMS) ((float4*)g_h)[a * 16 + cr] = v;
            *(float4*)(sSrc + (ar * 4 + i) * 64 + cr * 4) = v;   // h into sSrc
        }
    }
    __syncthreads();

    // u = h @ piW1_top + pib1
    for (int i = tid; i < 4096; i += 256) sW[i] = piw1[i];
    __syncthreads();
    {
        float acc[4][4];
#pragma unroll
        for (int i = 0; i < 4; i++) { acc[i][0] = acc[i][1] = acc[i][2] = acc[i][3] = 0.f; }
        const float* A = sSrc + ar * 4 * 64;
        const float* W = sW + cr * 4;
#pragma unroll 4
        for (int k4 = 0; k4 < 16; k4++) mm4(acc, A, 64, W, 64, k4);
        float4 bv = *(const float4*)(sB1 + cr * 4);
#pragma unroll
        for (int i = 0; i < 4; i++) {
            int a = abase + ar * 4 + i;
            if (a < NATOMS) {
                float4 v;
                v.x = acc[i][0] + bv.x; v.y = acc[i][1] + bv.y;
                v.z = acc[i][2] + bv.z; v.w = acc[i][3] + bv.w;
                ((float4*)g_u)[a * 16 + cr] = v;
            }
        }
    }
    __syncthreads();

    // v = h @ piW1_bot
    for (int i = tid; i < 4096; i += 256) sW[i] = piw1[4096 + i];
    __syncthreads();
    {
        float acc[4][4];
#pragma unroll
        for (int i = 0; i < 4; i++) { acc[i][0] = acc[i][1] = acc[i][2] = acc[i][3] = 0.f; }
        const float* A = sSrc + ar * 4 * 64;
        const float* W = sW + cr * 4;
#pragma unroll 4
        for (int k4 = 0; k4 < 16; k4++) mm4(acc, A, 64, W, 64, k4);
#pragma unroll
        for (int i = 0; i < 4; i++) {
            int a = abase + ar * 4 + i;
            if (a < NATOMS) {
                float4 v = make_float4(acc[i][0], acc[i][1], acc[i][2], acc[i][3]);
                ((float4*)g_v)[a * 16 + cr] = v;
            }
        }
    }
}

// ---------------------------------------------------------------------------
// Atom post-kernel: p update + output head accumulation (unchanged).
// ---------------------------------------------------------------------------
#define POST_SMEM_BYTES (12928 * 4)

__global__ __launch_bounds__(256, 1) void atom_post_kernel(
    const float* __restrict__ prop, const float* __restrict__ res0w,
    const float* __restrict__ w1, const float* __restrict__ b1,
    const float* __restrict__ w2, const float* __restrict__ b2,
    const float* __restrict__ wo, float* __restrict__ out, int d)
{
    extern __shared__ float sm[];
    float* bufA = sm;
    float* bufB = sm + 4352;
    float* sW   = sm + 8704;
    float* sB   = sm + 12800;
    float* sWo  = sm + 12864;

    const int tid = threadIdx.x;
    const int abase = blockIdx.x * 64;
    const int ar = tid >> 4, cr = tid & 15;

    float pn[4][4];
#pragma unroll
    for (int i = 0; i < 4; i++) { pn[i][0] = pn[i][1] = pn[i][2] = pn[i][3] = 0.f; }

    if (d == 0) {
        for (int i = tid; i < 1024; i += 256) sW[i] = res0w[i];
        for (int i = tid; i < 256; i += 256) {
            int a = i >> 2, seg = i & 3;
            float4 v = make_float4(0.f, 0.f, 0.f, 0.f);
            if (abase + a < NATOMS) v = ((const float4*)prop)[(abase + a) * 4 + seg];
            *(float4*)(bufB + a * 16 + seg * 4) = v;
        }
        __syncthreads();
        const float* A = bufB + ar * 4 * 16;
        const float* W = sW + cr * 4;
#pragma unroll
        for (int k4 = 0; k4 < 4; k4++) mm4(pn, A, 16, W, 64, k4);
    }

#pragma unroll
    for (int i = 0; i < 4; i++) {
        int a = abase + ar * 4 + i;
        float4 v = make_float4(0.f, 0.f, 0.f, 0.f);
        if (a < NATOMS) {
            float4 np = ((const float4*)g_newp)[a * 16 + cr];
            if (d == 0) {
                v.x = pn[i][0] + np.x; v.y = pn[i][1] + np.y;
                v.z = pn[i][2] + np.z; v.w = pn[i][3] + np.w;
            } else {
                float4 pv = ((const float4*)g_p)[a * 16 + cr];
                v.x = pv.x + np.x; v.y = pv.y + np.y;
                v.z = pv.z + np.z; v.w = pv.w + np.w;
            }
            ((float4*)g_p)[a * 16 + cr] = v;
        }
        *(float4*)(bufA + (ar * 4 + i) * 68 + cr * 4) = v;
    }
    __syncthreads();

    for (int i = tid; i < 4096; i += 256) sW[i] = w1[i];
    if (tid < 64) { sB[tid] = b1[tid]; sWo[tid] = wo[tid]; }
    __syncthreads();

    {
        float acc[4][4];
#pragma unroll
        for (int i = 0; i < 4; i++) { acc[i][0] = acc[i][1] = acc[i][2] = acc[i][3] = 0.f; }
        const float* A = bufA + ar * 4 * 68;
        const float* W = sW + cr * 4;
#pragma unroll 4
        for (int k4 = 0; k4 < 16; k4++) mm4(acc, A, 68, W, 64, k4);
        float4 bv = *(const float4*)(sB + cr * 4);
#pragma unroll
        for (int i = 0; i < 4; i++) {
            float4 v;
            v.x = tfast(acc[i][0] + bv.x); v.y = tfast(acc[i][1] + bv.y);
            v.z = tfast(acc[i][2] + bv.z); v.w = tfast(acc[i][3] + bv.w);
            *(float4*)(bufB + (ar * 4 + i) * 68 + cr * 4) = v;
        }
    }
    __syncthreads();
    for (int i = tid; i < 4096; i += 256) sW[i] = w2[i];
    if (tid < 64) sB[tid] = b2[tid];
    __syncthreads();

    {
        float acc[4][4];
#pragma unroll
        for (int i = 0; i < 4; i++) { acc[i][0] = acc[i][1] = acc[i][2] = acc[i][3] = 0.f; }
        const float* A = bufB + ar * 4 * 68;
        const float* W = sW + cr * 4;
#pragma unroll 4
        for (int k4 = 0; k4 < 16; k4++) mm4(acc, A, 68, W, 64, k4);
        float4 bv = *(const float4*)(sB + cr * 4);
#pragma unroll
        for (int i = 0; i < 4; i++) {
            float4 v;
            v.x = tfast(acc[i][0] + bv.x); v.y = tfast(acc[i][1] + bv.y);
            v.z = tfast(acc[i][2] + bv.z); v.w = tfast(acc[i][3] + bv.w);
            *(float4*)(bufA + (ar * 4 + i) * 68 + cr * 4) = v;
        }
    }
    __syncthreads();

    if (tid < 64) {
        int a = abase + tid;
        if (a < NATOMS) {
            float s = 0.f;
            const float* row = bufA + tid * 68;
#pragma unroll 8
            for (int c = 0; c < 64; c++) s = fmaf(row[c], sWo[c], s);
            out[a] = (d == 0) ? s : (out[a] + s);
        }
    }
}

// ---------------------------------------------------------------------------
extern "C" void kernel_launch(void* const* d_in, const int* in_sizes, int n_in,
                              void* d_out, int out_size) {
    const int*   ind2   = (const int*)d_in[0];
    const float* prop   = (const float*)d_in[1];
    const float* basis  = (const float*)d_in[2];
    const float* pp0_w1 = (const float*)d_in[3];
    const float* pp0_b1 = (const float*)d_in[4];
    const float* pp_w1  = (const float*)d_in[5];
    const float* pp_b1  = (const float*)d_in[6];
    const float* pp_w2  = (const float*)d_in[7];
    const float* pp_b2  = (const float*)d_in[8];
    const float* pi_w1  = (const float*)d_in[9];
    const float* pi_b1  = (const float*)d_in[10];
    const float* pi_w2  = (const float*)d_in[11];
    const float* pi_b2  = (const float*)d_in[12];
    const float* ii_w1  = (const float*)d_in[13];
    const float* ii_w2  = (const float*)d_in[14];
    const float* res0   = (const float*)d_in[15];
    const float* ow1    = (const float*)d_in[16];
    const float* ob1    = (const float*)d_in[17];
    const float* ow2    = (const float*)d_in[18];
    const float* ob2    = (const float*)d_in[19];
    const float* owo    = (const float*)d_in[20];
    float* out = (float*)d_out;

    static bool inited = false;
    if (!inited) {
        cudaFuncSetAttribute(pair_mma, cudaFuncAttributeMaxDynamicSharedMemorySize, PAIR_SMEM_BYTES);
        cudaFuncSetAttribute(atom_pre_kernel, cudaFuncAttributeMaxDynamicSharedMemorySize, PRE_SMEM_BYTES);
        cudaFuncSetAttribute(atom_post_kernel, cudaFuncAttributeMaxDynamicSharedMemorySize, POST_SMEM_BYTES);
        inited = true;
    }

    const int atom_blocks = (NATOMS + 63) / 64;     // 391
    const int pair_blocks = (NPAIRS + 127) / 128;   // 3907

    for (int d = 0; d < 4; d++) {
        const float* w1 = (d == 0) ? pp0_w1 : pp_w1 + (d - 1) * 4096;
        const float* b1 = (d == 0) ? pp0_b1 : pp_b1 + (d - 1) * 64;
        atom_pre_kernel<<<atom_blocks, 256, PRE_SMEM_BYTES>>>(
            prop, d, w1, b1, pp_w2 + d * 4096, pp_b2 + d * 64,
            pi_w1 + d * 8192, pi_b1 + d * 64);
        pair_mma<<<pair_blocks, 256, PAIR_SMEM_BYTES>>>(
            ind2, basis,
            pi_w2 + d * 16384, pi_b2 + d * 256,
            ii_w1 + d * 4096, ii_w2 + d * 4096);
        atom_post_kernel<<<atom_blocks, 256, POST_SMEM_BYTES>>>(
            prop, res0,
            ow1 + d * 4096, ob1 + d * 64,
            ow2 + d * 4096, ob2 + d * 64,
            owo + d * 64, out, d);
    }
}

// round 7
// speedup vs baseline: 2.2997x; 1.1456x over previous
#include <cuda_runtime.h>
#include <cuda_fp16.h>
#include <cstdint>

#define NATOMS 25000
#define NPAIRS 500000

__device__ __align__(16) float g_h[NATOMS * 64];
__device__ __align__(16) float g_p[NATOMS * 64];
__device__ __align__(16) float g_newp[NATOMS * 64];
__device__ __align__(16) float g_u[NATOMS * 64];
__device__ __align__(16) float g_v[NATOMS * 64];
// pre-converted weight fragments (per depth, refreshed by prep_kernel)
__device__ __align__(16) uint32_t g_w2H[8192], g_w2L[8192];
__device__ __align__(16) uint32_t g_wi1H[2048], g_wi1L[2048];
__device__ __align__(16) uint32_t g_wi2H[2048], g_wi2L[2048];
// inter activations, pre-split fp16 hi/lo (pad 128 rows for pairB's last block)
__device__ __align__(16) uint32_t g_intH[(NPAIRS + 128) * 32];
__device__ __align__(16) uint32_t g_intL[(NPAIRS + 128) * 32];

// accurate tanh: 1 - 2/(e^{2x}+1)  (~1e-6 rel err)
__device__ __forceinline__ float tfast(float x) {
    x = fminf(fmaxf(x, -15.f), 15.f);
    float e = __expf(2.f * x);
    return 1.f - __fdividef(2.f, e + 1.f);
}

// split two fp32 into packed fp16x2 hi + fp16x2 lo (3xFP16 compensation)
__device__ __forceinline__ void split2(float x0, float x1, uint32_t& H, uint32_t& L) {
    __half h0 = __float2half_rn(x0), h1 = __float2half_rn(x1);
    float r0 = x0 - __half2float(h0);
    float r1 = x1 - __half2float(h1);
    __half2 hh = __halves2half2(h0, h1);
    __half2 ll = __halves2half2(__float2half_rn(r0), __float2half_rn(r1));
    H = *reinterpret_cast<uint32_t*>(&hh);
    L = *reinterpret_cast<uint32_t*>(&ll);
}

__device__ __forceinline__ void mma16(float* d, uint32_t a0, uint32_t a1, uint32_t a2,
                                      uint32_t a3, uint32_t b0, uint32_t b1) {
    asm volatile("mma.sync.aligned.m16n8k16.row.col.f32.f16.f16.f32 "
        "{%0,%1,%2,%3}, {%4,%5,%6,%7}, {%8,%9}, {%0,%1,%2,%3};"
        : "+f"(d[0]), "+f"(d[1]), "+f"(d[2]), "+f"(d[3])
        : "r"(a0), "r"(a1), "r"(a2), "r"(a3), "r"(b0), "r"(b1));
}

// ---------------------------------------------------------------------------
// 3-term fp16 warp GEMM: 32 rows x 32 cols (4 n8-tiles from tileBase), K=16*KC.
// A: packed fp16x2 hi/lo arrays, word (row, kp) at row*32 + (kp ^ ((row&7)<<2)).
// acc += Ah*Bh + Ah*Bl + Al*Bh.
// ---------------------------------------------------------------------------
template<int KC>
__device__ __forceinline__ void gemm16(const uint32_t* __restrict__ AH, const uint32_t* __restrict__ AL,
        const uint32_t* __restrict__ WH, const uint32_t* __restrict__ WL,
        int r0, int tileBase, int lane, float acc[2][4][4])
{
    const int tig = lane & 3, gid = lane >> 2;
    const int sw = gid << 2;
#pragma unroll
    for (int kc = 0; kc < KC; kc++) {
        int k0 = (kc * 8 + tig) ^ sw;
        int k1 = (kc * 8 + tig + 4) ^ sw;
        uint32_t ah[2][4], al[2][4];
#pragma unroll
        for (int mt = 0; mt < 2; mt++) {
            const uint32_t* bh = AH + (r0 + mt * 16 + gid) * 32;
            const uint32_t* bl = AL + (r0 + mt * 16 + gid) * 32;
            ah[mt][0] = bh[k0]; ah[mt][1] = bh[256 + k0];
            ah[mt][2] = bh[k1]; ah[mt][3] = bh[256 + k1];
            al[mt][0] = bl[k0]; al[mt][1] = bl[256 + k0];
            al[mt][2] = bl[k1]; al[mt][3] = bl[256 + k1];
        }
#pragma unroll
        for (int nt = 0; nt < 4; nt++) {
            int wi = ((tileBase + nt) * KC + kc) * 64 + lane * 2;
            uint2 bh = *(const uint2*)(WH + wi);
            uint2 bl = *(const uint2*)(WL + wi);
#pragma unroll
            for (int mt = 0; mt < 2; mt++) {
                mma16(acc[mt][nt], ah[mt][0], ah[mt][1], ah[mt][2], ah[mt][3], bh.x, bh.y);
                mma16(acc[mt][nt], ah[mt][0], ah[mt][1], ah[mt][2], ah[mt][3], bl.x, bl.y);
                mma16(acc[mt][nt], al[mt][0], al[mt][1], al[mt][2], al[mt][3], bh.x, bh.y);
            }
        }
    }
}

// ---------------------------------------------------------------------------
// prep: convert depth-d weights into fragment-ordered hi/lo global arrays;
// zero the inter pad rows. Deterministic, runs every depth.
// ---------------------------------------------------------------------------
__global__ void prep_kernel(const float* __restrict__ w2,
                            const float* __restrict__ wi1, const float* __restrict__ wi2) {
    int tid = blockIdx.x * blockDim.x + threadIdx.x;
    int stride = gridDim.x * blockDim.x;
    for (int idx = tid; idx < 4096; idx += stride) {
        int lane = idx & 31, kc = (idx >> 5) & 3, t = idx >> 7;
        int n = t * 8 + (lane >> 2);
        int k0 = kc * 16 + 2 * (lane & 3);
        int o = (t * 4 + kc) * 64 + lane * 2;
        uint32_t h, l;
        split2(w2[k0 * 256 + n], w2[(k0 + 1) * 256 + n], h, l);
        g_w2H[o] = h; g_w2L[o] = l;
        split2(w2[(k0 + 8) * 256 + n], w2[(k0 + 9) * 256 + n], h, l);
        g_w2H[o + 1] = h; g_w2L[o + 1] = l;
    }
    for (int idx = tid; idx < 1024; idx += stride) {
        int lane = idx & 31, kc = (idx >> 5) & 3, t = idx >> 7;
        int n = t * 8 + (lane >> 2);
        int k0 = kc * 16 + 2 * (lane & 3);
        int o = (t * 4 + kc) * 64 + lane * 2;
        uint32_t h, l;
        split2(wi1[k0 * 64 + n], wi1[(k0 + 1) * 64 + n], h, l);
        g_wi1H[o] = h; g_wi1L[o] = l;
        split2(wi1[(k0 + 8) * 64 + n], wi1[(k0 + 9) * 64 + n], h, l);
        g_wi1H[o + 1] = h; g_wi1L[o + 1] = l;
        split2(wi2[k0 * 64 + n], wi2[(k0 + 1) * 64 + n], h, l);
        g_wi2H[o] = h; g_wi2L[o] = l;
        split2(wi2[(k0 + 8) * 64 + n], wi2[(k0 + 9) * 64 + n], h, l);
        g_wi2H[o + 1] = h; g_wi2L[o + 1] = l;
    }
    for (int i = tid; i < 4096; i += stride) {
        g_intH[NPAIRS * 32 + i] = 0;
        g_intL[NPAIRS * 32 + i] = 0;
    }
}

// ---------------------------------------------------------------------------
// pairA: 64 pairs/CTA. gather+tanh -> stage2 GEMM + basis contract -> g_int.
// ---------------------------------------------------------------------------
#define A_W2H  0
#define A_W2L  8192
#define A_WW1H 16384
#define A_WW1L 18432
#define A_INTH 20480
#define A_INTL 22528
#define A_BAS  24576   // 256 floats
#define A_B2   24832   // 256 floats
#define A_SMEM_BYTES (25088 * 4)

__global__ __launch_bounds__(256, 2) void pairA(
    const int* __restrict__ ind2, const float* __restrict__ basis,
    const float* __restrict__ b2)
{
    extern __shared__ uint32_t smw[];
    float* smf = (float*)smw;
    const int tid = threadIdx.x;
    const int pairbase = blockIdx.x * 64;

    for (int i = tid; i < 2048; i += 256) ((uint4*)(smw + A_W2H))[i] = ((const uint4*)g_w2H)[i];
    for (int i = tid; i < 2048; i += 256) ((uint4*)(smw + A_W2L))[i] = ((const uint4*)g_w2L)[i];
    if (tid < 128) { smf[A_B2 + tid] = b2[tid]; smf[A_B2 + 128 + tid] = b2[128 + tid]; }
    if (tid < 64) {
        int p = pairbase + tid;
        float4 bs = make_float4(0.f, 0.f, 0.f, 0.f);
        if (p < NPAIRS) bs = ((const float4*)basis)[p];
        ((float4*)(smf + A_BAS))[tid] = bs;
    }
    // stage 1: ww1 = tanh(u[i] + v[j]) -> packed hi/lo
#pragma unroll
    for (int r = 0; r < 8; r++) {
        int idx = tid + r * 256;             // 0..2047
        int row = idx >> 5, kp = idx & 31;
        int gp = pairbase + row;
        float x0 = 0.f, x1 = 0.f;
        if (gp < NPAIRS) {
            int ai = ind2[2 * gp], aj = ind2[2 * gp + 1];
            float2 u = *(const float2*)&g_u[ai * 64 + 2 * kp];
            float2 v = *(const float2*)&g_v[aj * 64 + 2 * kp];
            x0 = tfast(u.x + v.x);
            x1 = tfast(u.y + v.y);
        }
        uint32_t H, L; split2(x0, x1, H, L);
        int o = row * 32 + (kp ^ ((row & 7) << 2));
        smw[A_WW1H + o] = H; smw[A_WW1L + o] = L;
    }
    __syncthreads();

    const int lane = tid & 31, w = tid >> 5;
    const int rg = w & 1, cg = w >> 1;       // 2 row-groups x 4 col-groups
    const int r0 = rg * 32;
    const int tig = lane & 3, gid = lane >> 2;

    float4 bsv[4];
#pragma unroll
    for (int q = 0; q < 4; q++) bsv[q] = ((float4*)(smf + A_BAS))[r0 + gid + q * 8];
#pragma unroll 1
    for (int j = 0; j < 2; j++) {
        int g = cg + 4 * j;                  // col group 0..7
        float acc[2][4][4];
#pragma unroll
        for (int a = 0; a < 2; a++)
#pragma unroll
            for (int b = 0; b < 4; b++)
#pragma unroll
                for (int q = 0; q < 4; q++) acc[a][b][q] = 0.f;
        gemm16<4>(smw + A_WW1H, smw + A_WW1L, smw + A_W2H, smw + A_W2L, r0, g * 4, lane, acc);
#pragma unroll
        for (int mt = 0; mt < 2; mt++)
#pragma unroll
            for (int nt = 0; nt < 4; nt++) {
                int c0 = g * 32 + nt * 8 + 2 * tig;
                float b20 = smf[A_B2 + c0], b21 = smf[A_B2 + c0 + 1];
                float4 bL = bsv[mt * 2], bH = bsv[mt * 2 + 1];
                float cL0 = (tig & 1) ? bL.z : bL.x, cL1 = (tig & 1) ? bL.w : bL.y;
                float cH0 = (tig & 1) ? bH.z : bH.x, cH1 = (tig & 1) ? bH.w : bH.y;
                float pl = tfast(acc[mt][nt][0] + b20) * cL0 + tfast(acc[mt][nt][1] + b21) * cL1;
                float ph = tfast(acc[mt][nt][2] + b20) * cH0 + tfast(acc[mt][nt][3] + b21) * cH1;
                pl += __shfl_xor_sync(0xffffffffu, pl, 1);
                ph += __shfl_xor_sync(0xffffffffu, ph, 1);
                float pl2 = __shfl_xor_sync(0xffffffffu, pl, 2);
                float ph2 = __shfl_xor_sync(0xffffffffu, ph, 2);
                if (tig == 0) {
                    int kp = g * 4 + nt;
                    int rL = r0 + mt * 16 + gid, rH = rL + 8;
                    uint32_t H, L;
                    split2(pl, pl2, H, L);
                    int o = rL * 32 + (kp ^ (gid << 2));
                    smw[A_INTH + o] = H; smw[A_INTL + o] = L;
                    split2(ph, ph2, H, L);
                    o = rH * 32 + (kp ^ (gid << 2));
                    smw[A_INTH + o] = H; smw[A_INTL + o] = L;
                }
            }
    }
    __syncthreads();
    // coalesced dump of inter to global scratch
    for (int i = tid; i < 512; i += 256) {
        ((uint4*)(g_intH + pairbase * 32))[i] = ((uint4*)(smw + A_INTH))[i];
        ((uint4*)(g_intL + pairbase * 32))[i] = ((uint4*)(smw + A_INTL))[i];
    }
}

// ---------------------------------------------------------------------------
// pairB: 128 pairs/CTA. stage3 GEMM -> t1 -> stage4 GEMM -> atomic scatter.
// ---------------------------------------------------------------------------
#define B_INTH 0
#define B_INTL 4096
#define B_T1H  8192
#define B_T1L  12288
#define B_WI1H 16384
#define B_WI1L 18432
#define B_WI2H 20480
#define B_WI2L 22528
#define B_IDX  24576   // 128 int
#define B_SMEM_BYTES (24704 * 4)

__global__ __launch_bounds__(256, 2) void pairB(const int* __restrict__ ind2)
{
    extern __shared__ uint32_t smw[];
    const int tid = threadIdx.x;
    const int pairbase = blockIdx.x * 128;

    for (int i = tid; i < 1024; i += 256) {
        ((uint4*)(smw + B_INTH))[i] = ((const uint4*)(g_intH + pairbase * 32))[i];
        ((uint4*)(smw + B_INTL))[i] = ((const uint4*)(g_intL + pairbase * 32))[i];
    }
    for (int i = tid; i < 512; i += 256) {
        ((uint4*)(smw + B_WI1H))[i] = ((const uint4*)g_wi1H)[i];
        ((uint4*)(smw + B_WI1L))[i] = ((const uint4*)g_wi1L)[i];
        ((uint4*)(smw + B_WI2H))[i] = ((const uint4*)g_wi2H)[i];
        ((uint4*)(smw + B_WI2L))[i] = ((const uint4*)g_wi2L)[i];
    }
    if (tid < 128) {
        int p = pairbase + tid;
        ((int*)(smw + B_IDX))[tid] = (p < NPAIRS) ? ind2[2 * p] : -1;
    }
    __syncthreads();

    const int lane = tid & 31, w = tid >> 5;
    const int rg = w & 3, cg = w >> 2;       // 4 row-groups x 2 col-groups
    const int r0 = rg * 32;
    const int tig = lane & 3, gid = lane >> 2;

    // ---- stage 3: t1 = tanh(inter @ ii_w1) ----
    {
        float acc[2][4][4];
#pragma unroll
        for (int a = 0; a < 2; a++)
#pragma unroll
            for (int b = 0; b < 4; b++)
#pragma unroll
                for (int q = 0; q < 4; q++) acc[a][b][q] = 0.f;
        gemm16<4>(smw + B_INTH, smw + B_INTL, smw + B_WI1H, smw + B_WI1L, r0, cg * 4, lane, acc);
#pragma unroll
        for (int mt = 0; mt < 2; mt++)
#pragma unroll
            for (int nt = 0; nt < 4; nt++) {
                int kp = cg * 16 + nt * 4 + tig;
                int rL = r0 + mt * 16 + gid, rH = rL + 8;
                uint32_t H, L;
                split2(tfast(acc[mt][nt][0]), tfast(acc[mt][nt][1]), H, L);
                int o = rL * 32 + (kp ^ (gid << 2));
                smw[B_T1H + o] = H; smw[B_T1L + o] = L;
                split2(tfast(acc[mt][nt][2]), tfast(acc[mt][nt][3]), H, L);
                o = rH * 32 + (kp ^ (gid << 2));
                smw[B_T1H + o] = H; smw[B_T1L + o] = L;
            }
    }
    __syncthreads();

    // ---- stage 4: t2 = tanh(t1 @ ii_w2); scatter into g_newp[ind_i] ----
    {
        float acc[2][4][4];
#pragma unroll
        for (int a = 0; a < 2; a++)
#pragma unroll
            for (int b = 0; b < 4; b++)
#pragma unroll
                for (int q = 0; q < 4; q++) acc[a][b][q] = 0.f;
        gemm16<4>(smw + B_T1H, smw + B_T1L, smw + B_WI2H, smw + B_WI2L, r0, cg * 4, lane, acc);
        const int* idxI = (const int*)(smw + B_IDX);
#pragma unroll
        for (int mt = 0; mt < 2; mt++)
#pragma unroll
            for (int nt = 0; nt < 4; nt++) {
                int c0 = cg * 32 + nt * 8 + 2 * tig;
                int rL = r0 + mt * 16 + gid, rH = rL + 8;
                int aL = idxI[rL], aH = idxI[rH];
                if (aL >= 0) {
                    atomicAdd(&g_newp[aL * 64 + c0    ], tfast(acc[mt][nt][0]));
                    atomicAdd(&g_newp[aL * 64 + c0 + 1], tfast(acc[mt][nt][1]));
                }
                if (aH >= 0) {
                    atomicAdd(&g_newp[aH * 64 + c0    ], tfast(acc[mt][nt][2]));
                    atomicAdd(&g_newp[aH * 64 + c0 + 1], tfast(acc[mt][nt][3]));
                }
            }
    }
}

// ---------------------------------------------------------------------------
// fp32 4x4 register-tile helper for atom kernels
// ---------------------------------------------------------------------------
__device__ __forceinline__ void mm4(float acc[4][4], const float* __restrict__ A, int lda,
                                    const float* __restrict__ W, int ldw, int k4) {
    float4 w0 = *(const float4*)(W + (k4 * 4 + 0) * ldw);
    float4 w1 = *(const float4*)(W + (k4 * 4 + 1) * ldw);
    float4 w2 = *(const float4*)(W + (k4 * 4 + 2) * ldw);
    float4 w3 = *(const float4*)(W + (k4 * 4 + 3) * ldw);
#pragma unroll
    for (int i = 0; i < 4; i++) {
        float4 a = *(const float4*)(A + i * lda + k4 * 4);
        acc[i][0] = fmaf(a.x, w0.x, fmaf(a.y, w1.x, fmaf(a.z, w2.x, fmaf(a.w, w3.x, acc[i][0]))));
        acc[i][1] = fmaf(a.x, w0.y, fmaf(a.y, w1.y, fmaf(a.z, w2.y, fmaf(a.w, w3.y, acc[i][1]))));
        acc[i][2] = fmaf(a.x, w0.z, fmaf(a.y, w1.z, fmaf(a.z, w2.z, fmaf(a.w, w3.z, acc[i][2]))));
        acc[i][3] = fmaf(a.x, w0.w, fmaf(a.y, w1.w, fmaf(a.z, w2.w, fmaf(a.w, w3.w, acc[i][3]))));
    }
}

// ---------------------------------------------------------------------------
// Atom pre-kernel: h = tanh(tanh(p@W1+b1)@W2+b2); u = h@piW1_top + pib1;
// v = h@piW1_bot. Also zeroes g_newp.
// ---------------------------------------------------------------------------
#define PRE_SMEM_BYTES (12416 * 4)

__global__ __launch_bounds__(256, 1) void atom_pre_kernel(
    const float* __restrict__ prop, int d,
    const float* __restrict__ w1, const float* __restrict__ b1,
    const float* __restrict__ w2, const float* __restrict__ b2,
    const float* __restrict__ piw1, const float* __restrict__ pib1)
{
    extern __shared__ float sm[];
    float* sSrc = sm;
    float* sW   = sm + 4096;
    float* sH   = sm + 8192;
    float* sB   = sm + 12288;
    float* sB1  = sm + 12352;

    const int tid = threadIdx.x;
    const int abase = blockIdx.x * 64;
    const int K0 = (d == 0) ? 16 : 64;
    const int kq = K0 >> 2;
    const float* src = (d == 0) ? prop : g_p;

    for (int i = tid; i < K0 * 64; i += 256) sW[i] = w1[i];
    if (tid < 64) { sB[tid] = b1[tid]; sB1[tid] = pib1[tid]; }
    for (int i = tid; i < 64 * kq; i += 256) {
        int a = i / kq, seg = i % kq;
        float4 v = make_float4(0.f, 0.f, 0.f, 0.f);
        if (abase + a < NATOMS) v = ((const float4*)src)[(abase + a) * kq + seg];
        *(float4*)(sSrc + a * 64 + seg * 4) = v;
    }
    for (int i = tid; i < 1024; i += 256) {
        int a = i >> 4;
        if (abase + a < NATOMS)
            ((float4*)g_newp)[(abase + a) * 16 + (i & 15)] = make_float4(0.f, 0.f, 0.f, 0.f);
    }
    __syncthreads();

    const int ar = tid >> 4, cr = tid & 15;
    {
        float acc[4][4];
#pragma unroll
        for (int i = 0; i < 4; i++) { acc[i][0] = acc[i][1] = acc[i][2] = acc[i][3] = 0.f; }
        const float* A = sSrc + ar * 4 * 64;
        const float* W = sW + cr * 4;
        for (int k4 = 0; k4 < kq; k4++) mm4(acc, A, 64, W, 64, k4);
        float4 bv = *(const float4*)(sB + cr * 4);
#pragma unroll
        for (int i = 0; i < 4; i++) {
            float4 v;
            v.x = tfast(acc[i][0] + bv.x); v.y = tfast(acc[i][1] + bv.y);
            v.z = tfast(acc[i][2] + bv.z); v.w = tfast(acc[i][3] + bv.w);
            *(float4*)(sH + (ar * 4 + i) * 64 + cr * 4) = v;
        }
    }
    __syncthreads();
    for (int i = tid; i < 4096; i += 256) sW[i] = w2[i];
    if (tid < 64) sB[tid] = b2[tid];
    __syncthreads();
    {
        float acc[4][4];
#pragma unroll
        for (int i = 0; i < 4; i++) { acc[i][0] = acc[i][1] = acc[i][2] = acc[i][3] = 0.f; }
        const float* A = sH + ar * 4 * 64;
        const float* W = sW + cr * 4;
#pragma unroll 4
        for (int k4 = 0; k4 < 16; k4++) mm4(acc, A, 64, W, 64, k4);
        float4 bv = *(const float4*)(sB + cr * 4);
#pragma unroll
        for (int i = 0; i < 4; i++) {
            int a = abase + ar * 4 + i;
            float4 v;
            v.x = tfast(acc[i][0] + bv.x); v.y = tfast(acc[i][1] + bv.y);
            v.z = tfast(acc[i][2] + bv.z); v.w = tfast(acc[i][3] + bv.w);
            if (a < NATOMS) ((float4*)g_h)[a * 16 + cr] = v;
            *(float4*)(sSrc + (ar * 4 + i) * 64 + cr * 4) = v;
        }
    }
    __syncthreads();

    // u = h @ piW1_top + pib1
    for (int i = tid; i < 4096; i += 256) sW[i] = piw1[i];
    __syncthreads();
    {
        float acc[4][4];
#pragma unroll
        for (int i = 0; i < 4; i++) { acc[i][0] = acc[i][1] = acc[i][2] = acc[i][3] = 0.f; }
        const float* A = sSrc + ar * 4 * 64;
        const float* W = sW + cr * 4;
#pragma unroll 4
        for (int k4 = 0; k4 < 16; k4++) mm4(acc, A, 64, W, 64, k4);
        float4 bv = *(const float4*)(sB1 + cr * 4);
#pragma unroll
        for (int i = 0; i < 4; i++) {
            int a = abase + ar * 4 + i;
            if (a < NATOMS) {
                float4 v;
                v.x = acc[i][0] + bv.x; v.y = acc[i][1] + bv.y;
                v.z = acc[i][2] + bv.z; v.w = acc[i][3] + bv.w;
                ((float4*)g_u)[a * 16 + cr] = v;
            }
        }
    }
    __syncthreads();

    // v = h @ piW1_bot
    for (int i = tid; i < 4096; i += 256) sW[i] = piw1[4096 + i];
    __syncthreads();
    {
        float acc[4][4];
#pragma unroll
        for (int i = 0; i < 4; i++) { acc[i][0] = acc[i][1] = acc[i][2] = acc[i][3] = 0.f; }
        const float* A = sSrc + ar * 4 * 64;
        const float* W = sW + cr * 4;
#pragma unroll 4
        for (int k4 = 0; k4 < 16; k4++) mm4(acc, A, 64, W, 64, k4);
#pragma unroll
        for (int i = 0; i < 4; i++) {
            int a = abase + ar * 4 + i;
            if (a < NATOMS) {
                float4 v = make_float4(acc[i][0], acc[i][1], acc[i][2], acc[i][3]);
                ((float4*)g_v)[a * 16 + cr] = v;
            }
        }
    }
}

// ---------------------------------------------------------------------------
// Atom post-kernel: p update + output head accumulation.
// ---------------------------------------------------------------------------
#define POST_SMEM_BYTES (12928 * 4)

__global__ __launch_bounds__(256, 1) void atom_post_kernel(
    const float* __restrict__ prop, const float* __restrict__ res0w,
    const float* __restrict__ w1, const float* __restrict__ b1,
    const float* __restrict__ w2, const float* __restrict__ b2,
    const float* __restrict__ wo, float* __restrict__ out, int d)
{
    extern __shared__ float sm[];
    float* bufA = sm;
    float* bufB = sm + 4352;
    float* sW   = sm + 8704;
    float* sB   = sm + 12800;
    float* sWo  = sm + 12864;

    const int tid = threadIdx.x;
    const int abase = blockIdx.x * 64;
    const int ar = tid >> 4, cr = tid & 15;

    float pn[4][4];
#pragma unroll
    for (int i = 0; i < 4; i++) { pn[i][0] = pn[i][1] = pn[i][2] = pn[i][3] = 0.f; }

    if (d == 0) {
        for (int i = tid; i < 1024; i += 256) sW[i] = res0w[i];
        for (int i = tid; i < 256; i += 256) {
            int a = i >> 2, seg = i & 3;
            float4 v = make_float4(0.f, 0.f, 0.f, 0.f);
            if (abase + a < NATOMS) v = ((const float4*)prop)[(abase + a) * 4 + seg];
            *(float4*)(bufB + a * 16 + seg * 4) = v;
        }
        __syncthreads();
        const float* A = bufB + ar * 4 * 16;
        const float* W = sW + cr * 4;
#pragma unroll
        for (int k4 = 0; k4 < 4; k4++) mm4(pn, A, 16, W, 64, k4);
    }

#pragma unroll
    for (int i = 0; i < 4; i++) {
        int a = abase + ar * 4 + i;
        float4 v = make_float4(0.f, 0.f, 0.f, 0.f);
        if (a < NATOMS) {
            float4 np = ((const float4*)g_newp)[a * 16 + cr];
            if (d == 0) {
                v.x = pn[i][0] + np.x; v.y = pn[i][1] + np.y;
                v.z = pn[i][2] + np.z; v.w = pn[i][3] + np.w;
            } else {
                float4 pv = ((const float4*)g_p)[a * 16 + cr];
                v.x = pv.x + np.x; v.y = pv.y + np.y;
                v.z = pv.z + np.z; v.w = pv.w + np.w;
            }
            ((float4*)g_p)[a * 16 + cr] = v;
        }
        *(float4*)(bufA + (ar * 4 + i) * 68 + cr * 4) = v;
    }
    __syncthreads();

    for (int i = tid; i < 4096; i += 256) sW[i] = w1[i];
    if (tid < 64) { sB[tid] = b1[tid]; sWo[tid] = wo[tid]; }
    __syncthreads();

    {
        float acc[4][4];
#pragma unroll
        for (int i = 0; i < 4; i++) { acc[i][0] = acc[i][1] = acc[i][2] = acc[i][3] = 0.f; }
        const float* A = bufA + ar * 4 * 68;
        const float* W = sW + cr * 4;
#pragma unroll 4
        for (int k4 = 0; k4 < 16; k4++) mm4(acc, A, 68, W, 64, k4);
        float4 bv = *(const float4*)(sB + cr * 4);
#pragma unroll
        for (int i = 0; i < 4; i++) {
            float4 v;
            v.x = tfast(acc[i][0] + bv.x); v.y = tfast(acc[i][1] + bv.y);
            v.z = tfast(acc[i][2] + bv.z); v.w = tfast(acc[i][3] + bv.w);
            *(float4*)(bufB + (ar * 4 + i) * 68 + cr * 4) = v;
        }
    }
    __syncthreads();
    for (int i = tid; i < 4096; i += 256) sW[i] = w2[i];
    if (tid < 64) sB[tid] = b2[tid];
    __syncthreads();

    {
        float acc[4][4];
#pragma unroll
        for (int i = 0; i < 4; i++) { acc[i][0] = acc[i][1] = acc[i][2] = acc[i][3] = 0.f; }
        const float* A = bufB + ar * 4 * 68;
        const float* W = sW + cr * 4;
#pragma unroll 4
        for (int k4 = 0; k4 < 16; k4++) mm4(acc, A, 68, W, 64, k4);
        float4 bv = *(const float4*)(sB + cr * 4);
#pragma unroll
        for (int i = 0; i < 4; i++) {
            float4 v;
            v.x = tfast(acc[i][0] + bv.x); v.y = tfast(acc[i][1] + bv.y);
            v.z = tfast(acc[i][2] + bv.z); v.w = tfast(acc[i][3] + bv.w);
            *(float4*)(bufA + (ar * 4 + i) * 68 + cr * 4) = v;
        }
    }
    __syncthreads();

    if (tid < 64) {
        int a = abase + tid;
        if (a < NATOMS) {
            float s = 0.f;
            const float* row = bufA + tid * 68;
#pragma unroll 8
            for (int c = 0; c < 64; c++) s = fmaf(row[c], sWo[c], s);
            out[a] = (d == 0) ? s : (out[a] + s);
        }
    }
}

// ---------------------------------------------------------------------------
extern "C" void kernel_launch(void* const* d_in, const int* in_sizes, int n_in,
                              void* d_out, int out_size) {
    const int*   ind2   = (const int*)d_in[0];
    const float* prop   = (const float*)d_in[1];
    const float* basis  = (const float*)d_in[2];
    const float* pp0_w1 = (const float*)d_in[3];
    const float* pp0_b1 = (const float*)d_in[4];
    const float* pp_w1  = (const float*)d_in[5];
    const float* pp_b1  = (const float*)d_in[6];
    const float* pp_w2  = (const float*)d_in[7];
    const float* pp_b2  = (const float*)d_in[8];
    const float* pi_w1  = (const float*)d_in[9];
    const float* pi_b1  = (const float*)d_in[10];
    const float* pi_w2  = (const float*)d_in[11];
    const float* pi_b2  = (const float*)d_in[12];
    const float* ii_w1  = (const float*)d_in[13];
    const float* ii_w2  = (const float*)d_in[14];
    const float* res0   = (const float*)d_in[15];
    const float* ow1    = (const float*)d_in[16];
    const float* ob1    = (const float*)d_in[17];
    const float* ow2    = (const float*)d_in[18];
    const float* ob2    = (const float*)d_in[19];
    const float* owo    = (const float*)d_in[20];
    float* out = (float*)d_out;

    static bool inited = false;
    if (!inited) {
        cudaFuncSetAttribute(pairA, cudaFuncAttributeMaxDynamicSharedMemorySize, A_SMEM_BYTES);
        cudaFuncSetAttribute(pairB, cudaFuncAttributeMaxDynamicSharedMemorySize, B_SMEM_BYTES);
        cudaFuncSetAttribute(atom_pre_kernel, cudaFuncAttributeMaxDynamicSharedMemorySize, PRE_SMEM_BYTES);
        cudaFuncSetAttribute(atom_post_kernel, cudaFuncAttributeMaxDynamicSharedMemorySize, POST_SMEM_BYTES);
        inited = true;
    }

    const int atom_blocks = (NATOMS + 63) / 64;      // 391
    const int pairA_blocks = (NPAIRS + 63) / 64;     // 7813
    const int pairB_blocks = (NPAIRS + 127) / 128;   // 3907

    for (int d = 0; d < 4; d++) {
        const float* w1 = (d == 0) ? pp0_w1 : pp_w1 + (d - 1) * 4096;
        const float* b1 = (d == 0) ? pp0_b1 : pp_b1 + (d - 1) * 64;
        prep_kernel<<<16, 256>>>(pi_w2 + d * 16384, ii_w1 + d * 4096, ii_w2 + d * 4096);
        atom_pre_kernel<<<atom_blocks, 256, PRE_SMEM_BYTES>>>(
            prop, d, w1, b1, pp_w2 + d * 4096, pp_b2 + d * 64,
            pi_w1 + d * 8192, pi_b1 + d * 64);
        pairA<<<pairA_blocks, 256, A_SMEM_BYTES>>>(ind2, basis, pi_b2 + d * 256);
        pairB<<<pairB_blocks, 256, B_SMEM_BYTES>>>(ind2);
        atom_post_kernel<<<atom_blocks, 256, POST_SMEM_BYTES>>>(
            prop, res0,
            ow1 + d * 4096, ob1 + d * 64,
            ow2 + d * 4096, ob2 + d * 64,
            owo + d * 64, out, d);
    }
}

// round 8
// speedup vs baseline: 2.7894x; 1.2130x over previous
#include <cuda_runtime.h>
#include <cuda_fp16.h>
#include <cstdint>

#define NATOMS 25000
#define NPAIRS 500000
#define NBLKA 7813
#define NBLKB 3907

__device__ __align__(16) float g_h[NATOMS * 64];
__device__ __align__(16) float g_p[NATOMS * 64];
__device__ __align__(16) float g_newp[NATOMS * 64];
__device__ __align__(16) float g_u[NATOMS * 64];
__device__ __align__(16) float g_v[NATOMS * 64];
__device__ __align__(16) uint32_t g_w2H[8192], g_w2L[8192];
__device__ __align__(16) uint32_t g_wi1H[2048], g_wi1L[2048];
__device__ __align__(16) uint32_t g_wi2H[2048], g_wi2L[2048];
__device__ __align__(16) uint32_t g_intH[(NPAIRS + 128) * 32];
__device__ __align__(16) uint32_t g_intL[(NPAIRS + 128) * 32];

__device__ __forceinline__ float tfast(float x) {
    x = fminf(fmaxf(x, -15.f), 15.f);
    float e = __expf(2.f * x);
    return 1.f - __fdividef(2.f, e + 1.f);
}

__device__ __forceinline__ void split2(float x0, float x1, uint32_t& H, uint32_t& L) {
    __half h0 = __float2half_rn(x0), h1 = __float2half_rn(x1);
    float r0 = x0 - __half2float(h0);
    float r1 = x1 - __half2float(h1);
    __half2 hh = __halves2half2(h0, h1);
    __half2 ll = __halves2half2(__float2half_rn(r0), __float2half_rn(r1));
    H = *reinterpret_cast<uint32_t*>(&hh);
    L = *reinterpret_cast<uint32_t*>(&ll);
}

__device__ __forceinline__ void mma16(float* d, uint32_t a0, uint32_t a1, uint32_t a2,
                                      uint32_t a3, uint32_t b0, uint32_t b1) {
    asm volatile("mma.sync.aligned.m16n8k16.row.col.f32.f16.f16.f32 "
        "{%0,%1,%2,%3}, {%4,%5,%6,%7}, {%8,%9}, {%0,%1,%2,%3};"
        : "+f"(d[0]), "+f"(d[1]), "+f"(d[2]), "+f"(d[3])
        : "r"(a0), "r"(a1), "r"(a2), "r"(a3), "r"(b0), "r"(b1));
}

__device__ __forceinline__ void red4(float* p, float a, float b, float c, float d) {
    asm volatile("red.global.add.v4.f32 [%0], {%1,%2,%3,%4};"
        :: "l"(p), "f"(a), "f"(b), "f"(c), "f"(d) : "memory");
}

// 3-term fp16 warp GEMM: 32 rows x 32 cols, K=16*KC (see R6/R7).
template<int KC>
__device__ __forceinline__ void gemm16(const uint32_t* __restrict__ AH, const uint32_t* __restrict__ AL,
        const uint32_t* __restrict__ WH, const uint32_t* __restrict__ WL,
        int r0, int tileBase, int lane, float acc[2][4][4])
{
    const int tig = lane & 3, gid = lane >> 2;
    const int sw = gid << 2;
#pragma unroll
    for (int kc = 0; kc < KC; kc++) {
        int k0 = (kc * 8 + tig) ^ sw;
        int k1 = (kc * 8 + tig + 4) ^ sw;
        uint32_t ah[2][4], al[2][4];
#pragma unroll
        for (int mt = 0; mt < 2; mt++) {
            const uint32_t* bh = AH + (r0 + mt * 16 + gid) * 32;
            const uint32_t* bl = AL + (r0 + mt * 16 + gid) * 32;
            ah[mt][0] = bh[k0]; ah[mt][1] = bh[256 + k0];
            ah[mt][2] = bh[k1]; ah[mt][3] = bh[256 + k1];
            al[mt][0] = bl[k0]; al[mt][1] = bl[256 + k0];
            al[mt][2] = bl[k1]; al[mt][3] = bl[256 + k1];
        }
#pragma unroll
        for (int nt = 0; nt < 4; nt++) {
            int wi = ((tileBase + nt) * KC + kc) * 64 + lane * 2;
            uint2 bh = *(const uint2*)(WH + wi);
            uint2 bl = *(const uint2*)(WL + wi);
#pragma unroll
            for (int mt = 0; mt < 2; mt++) {
                mma16(acc[mt][nt], ah[mt][0], ah[mt][1], ah[mt][2], ah[mt][3], bh.x, bh.y);
                mma16(acc[mt][nt], ah[mt][0], ah[mt][1], ah[mt][2], ah[mt][3], bl.x, bl.y);
                mma16(acc[mt][nt], al[mt][0], al[mt][1], al[mt][2], al[mt][3], bh.x, bh.y);
            }
        }
    }
}

// ---------------------------------------------------------------------------
__global__ void prep_kernel(const float* __restrict__ w2,
                            const float* __restrict__ wi1, const float* __restrict__ wi2) {
    int tid = blockIdx.x * blockDim.x + threadIdx.x;
    int stride = gridDim.x * blockDim.x;
    for (int idx = tid; idx < 4096; idx += stride) {
        int lane = idx & 31, kc = (idx >> 5) & 3, t = idx >> 7;
        int n = t * 8 + (lane >> 2);
        int k0 = kc * 16 + 2 * (lane & 3);
        int o = (t * 4 + kc) * 64 + lane * 2;
        uint32_t h, l;
        split2(w2[k0 * 256 + n], w2[(k0 + 1) * 256 + n], h, l);
        g_w2H[o] = h; g_w2L[o] = l;
        split2(w2[(k0 + 8) * 256 + n], w2[(k0 + 9) * 256 + n], h, l);
        g_w2H[o + 1] = h; g_w2L[o + 1] = l;
    }
    for (int idx = tid; idx < 1024; idx += stride) {
        int lane = idx & 31, kc = (idx >> 5) & 3, t = idx >> 7;
        int n = t * 8 + (lane >> 2);
        int k0 = kc * 16 + 2 * (lane & 3);
        int o = (t * 4 + kc) * 64 + lane * 2;
        uint32_t h, l;
        split2(wi1[k0 * 64 + n], wi1[(k0 + 1) * 64 + n], h, l);
        g_wi1H[o] = h; g_wi1L[o] = l;
        split2(wi1[(k0 + 8) * 64 + n], wi1[(k0 + 9) * 64 + n], h, l);
        g_wi1H[o + 1] = h; g_wi1L[o + 1] = l;
        split2(wi2[k0 * 64 + n], wi2[(k0 + 1) * 64 + n], h, l);
        g_wi2H[o] = h; g_wi2L[o] = l;
        split2(wi2[(k0 + 8) * 64 + n], wi2[(k0 + 9) * 64 + n], h, l);
        g_wi2H[o + 1] = h; g_wi2L[o + 1] = l;
    }
    for (int i = tid; i < 4096; i += stride) {
        g_intH[NPAIRS * 32 + i] = 0;
        g_intL[NPAIRS * 32 + i] = 0;
    }
}

// ---------------------------------------------------------------------------
// pairA: persistent, 64 pairs/iter. gather+tanh -> stage2 GEMM+basis -> g_int.
// ---------------------------------------------------------------------------
#define A_W2H  0
#define A_W2L  8192
#define A_WW1H 16384
#define A_WW1L 18432
#define A_INTH 20480
#define A_INTL 22528
#define A_BAS  24576
#define A_B2   24832
#define A_SMEM_BYTES (25088 * 4)

__global__ __launch_bounds__(256, 2) void pairA(
    const int* __restrict__ ind2, const float* __restrict__ basis,
    const float* __restrict__ b2)
{
    extern __shared__ uint32_t smw[];
    float* smf = (float*)smw;
    const int tid = threadIdx.x;

    for (int i = tid; i < 2048; i += 256) ((uint4*)(smw + A_W2H))[i] = ((const uint4*)g_w2H)[i];
    for (int i = tid; i < 2048; i += 256) ((uint4*)(smw + A_W2L))[i] = ((const uint4*)g_w2L)[i];
    if (tid < 128) { smf[A_B2 + tid] = b2[tid]; smf[A_B2 + 128 + tid] = b2[128 + tid]; }

    const int lane = tid & 31, w = tid >> 5;
    const int rg = w & 1, cg = w >> 1;       // 2 row-groups x 4 col-groups
    const int r0 = rg * 32;
    const int tig = lane & 3, gid = lane >> 2;

    for (int blk = blockIdx.x; blk < NBLKA; blk += gridDim.x) {
        const int pairbase = blk * 64;
        __syncthreads();   // prior iteration's reads of WW1/BAS/INT done

        if (tid < 64) {
            int p = pairbase + tid;
            float4 bs = make_float4(0.f, 0.f, 0.f, 0.f);
            if (p < NPAIRS) bs = ((const float4*)basis)[p];
            ((float4*)(smf + A_BAS))[tid] = bs;
        }
        // stage 1: ww1 = tanh(u[i] + v[j]) -> packed hi/lo
#pragma unroll
        for (int r = 0; r < 8; r++) {
            int idx = tid + r * 256;
            int row = idx >> 5, kp = idx & 31;
            int gp = pairbase + row;
            float x0 = 0.f, x1 = 0.f;
            if (gp < NPAIRS) {
                int ai = ind2[2 * gp], aj = ind2[2 * gp + 1];
                float2 u = *(const float2*)&g_u[ai * 64 + 2 * kp];
                float2 v = *(const float2*)&g_v[aj * 64 + 2 * kp];
                x0 = tfast(u.x + v.x);
                x1 = tfast(u.y + v.y);
            }
            uint32_t H, L; split2(x0, x1, H, L);
            int o = row * 32 + (kp ^ ((row & 7) << 2));
            smw[A_WW1H + o] = H; smw[A_WW1L + o] = L;
        }
        __syncthreads();

        float4 bsv[4];
#pragma unroll
        for (int q = 0; q < 4; q++) bsv[q] = ((float4*)(smf + A_BAS))[r0 + gid + q * 8];
#pragma unroll 1
        for (int j = 0; j < 2; j++) {
            int g = cg + 4 * j;
            float acc[2][4][4];
#pragma unroll
            for (int a = 0; a < 2; a++)
#pragma unroll
                for (int b = 0; b < 4; b++)
#pragma unroll
                    for (int q = 0; q < 4; q++) acc[a][b][q] = 0.f;
            gemm16<4>(smw + A_WW1H, smw + A_WW1L, smw + A_W2H, smw + A_W2L, r0, g * 4, lane, acc);
#pragma unroll
            for (int mt = 0; mt < 2; mt++)
#pragma unroll
                for (int nt = 0; nt < 4; nt++) {
                    int c0 = g * 32 + nt * 8 + 2 * tig;
                    float b20 = smf[A_B2 + c0], b21 = smf[A_B2 + c0 + 1];
                    float4 bL = bsv[mt * 2], bH = bsv[mt * 2 + 1];
                    float cL0 = (tig & 1) ? bL.z : bL.x, cL1 = (tig & 1) ? bL.w : bL.y;
                    float cH0 = (tig & 1) ? bH.z : bH.x, cH1 = (tig & 1) ? bH.w : bH.y;
                    float pl = tfast(acc[mt][nt][0] + b20) * cL0 + tfast(acc[mt][nt][1] + b21) * cL1;
                    float ph = tfast(acc[mt][nt][2] + b20) * cH0 + tfast(acc[mt][nt][3] + b21) * cH1;
                    pl += __shfl_xor_sync(0xffffffffu, pl, 1);
                    ph += __shfl_xor_sync(0xffffffffu, ph, 1);
                    float pl2 = __shfl_xor_sync(0xffffffffu, pl, 2);
                    float ph2 = __shfl_xor_sync(0xffffffffu, ph, 2);
                    if (tig == 0) {
                        int kp = g * 4 + nt;
                        int rL = r0 + mt * 16 + gid, rH = rL + 8;
                        uint32_t H, L;
                        split2(pl, pl2, H, L);
                        int o = rL * 32 + (kp ^ (gid << 2));
                        smw[A_INTH + o] = H; smw[A_INTL + o] = L;
                        split2(ph, ph2, H, L);
                        o = rH * 32 + (kp ^ (gid << 2));
                        smw[A_INTH + o] = H; smw[A_INTL + o] = L;
                    }
                }
        }
        __syncthreads();
        for (int i = tid; i < 512; i += 256) {
            ((uint4*)(g_intH + pairbase * 32))[i] = ((uint4*)(smw + A_INTH))[i];
            ((uint4*)(g_intL + pairbase * 32))[i] = ((uint4*)(smw + A_INTL))[i];
        }
    }
}

// ---------------------------------------------------------------------------
// pairB: persistent, 128 pairs/iter, 3 CTAs/SM. inter -> t1 -> t2 -> red.v4.
// Region0 (8704 words) aliases: INT hi/lo -> T1 hi/lo -> t2 fp32 (stride 68).
// ---------------------------------------------------------------------------
#define B_R0   0
#define B_WI1H 8704
#define B_WI1L 10752
#define B_WI2H 12800
#define B_WI2L 14848
#define B_IDX  16896
#define B_SMEM_BYTES (17024 * 4)

__global__ __launch_bounds__(256, 3) void pairB(const int* __restrict__ ind2)
{
    extern __shared__ uint32_t smw[];
    float* smf = (float*)smw;
    const int tid = threadIdx.x;

    for (int i = tid; i < 512; i += 256) {
        ((uint4*)(smw + B_WI1H))[i] = ((const uint4*)g_wi1H)[i];
        ((uint4*)(smw + B_WI1L))[i] = ((const uint4*)g_wi1L)[i];
        ((uint4*)(smw + B_WI2H))[i] = ((const uint4*)g_wi2H)[i];
        ((uint4*)(smw + B_WI2L))[i] = ((const uint4*)g_wi2L)[i];
    }

    const int lane = tid & 31, w = tid >> 5;
    const int rg = w & 3, cg = w >> 2;       // 4 row-groups x 2 col-groups
    const int r0 = rg * 32;
    const int tig = lane & 3, gid = lane >> 2;

    for (int blk = blockIdx.x; blk < NBLKB; blk += gridDim.x) {
        const int pairbase = blk * 128;
        __syncthreads();   // prior iter scatter reads done before overwriting region0

        for (int i = tid; i < 1024; i += 256) {
            ((uint4*)(smw + B_R0))[i] = ((const uint4*)(g_intH + pairbase * 32))[i];
            ((uint4*)(smw + B_R0 + 4096))[i] = ((const uint4*)(g_intL + pairbase * 32))[i];
        }
        if (tid < 128) {
            int p = pairbase + tid;
            ((int*)(smw + B_IDX))[tid] = (p < NPAIRS) ? ind2[2 * p] : -1;
        }
        __syncthreads();

        // ---- stage 3: t1 = tanh(inter @ ii_w1) ----
        float acc[2][4][4];
#pragma unroll
        for (int a = 0; a < 2; a++)
#pragma unroll
            for (int b = 0; b < 4; b++)
#pragma unroll
                for (int q = 0; q < 4; q++) acc[a][b][q] = 0.f;
        gemm16<4>(smw + B_R0, smw + B_R0 + 4096, smw + B_WI1H, smw + B_WI1L, r0, cg * 4, lane, acc);
        __syncthreads();   // all reads of inter done
#pragma unroll
        for (int mt = 0; mt < 2; mt++)
#pragma unroll
            for (int nt = 0; nt < 4; nt++) {
                int kp = cg * 16 + nt * 4 + tig;
                int rL = r0 + mt * 16 + gid, rH = rL + 8;
                uint32_t H, L;
                split2(tfast(acc[mt][nt][0]), tfast(acc[mt][nt][1]), H, L);
                int o = rL * 32 + (kp ^ (gid << 2));
                smw[B_R0 + o] = H; smw[B_R0 + 4096 + o] = L;
                split2(tfast(acc[mt][nt][2]), tfast(acc[mt][nt][3]), H, L);
                o = rH * 32 + (kp ^ (gid << 2));
                smw[B_R0 + o] = H; smw[B_R0 + 4096 + o] = L;
            }
        __syncthreads();

        // ---- stage 4: t2 = tanh(t1 @ ii_w2) ----
#pragma unroll
        for (int a = 0; a < 2; a++)
#pragma unroll
            for (int b = 0; b < 4; b++)
#pragma unroll
                for (int q = 0; q < 4; q++) acc[a][b][q] = 0.f;
        gemm16<4>(smw + B_R0, smw + B_R0 + 4096, smw + B_WI2H, smw + B_WI2L, r0, cg * 4, lane, acc);
        __syncthreads();   // all reads of t1 done
#pragma unroll
        for (int mt = 0; mt < 2; mt++)
#pragma unroll
            for (int nt = 0; nt < 4; nt++) {
                int c0 = cg * 32 + nt * 8 + 2 * tig;
                int rL = r0 + mt * 16 + gid, rH = rL + 8;
                float2 v;
                v.x = tfast(acc[mt][nt][0]); v.y = tfast(acc[mt][nt][1]);
                *(float2*)&smf[rL * 68 + c0] = v;
                v.x = tfast(acc[mt][nt][2]); v.y = tfast(acc[mt][nt][3]);
                *(float2*)&smf[rH * 68 + c0] = v;
            }
        __syncthreads();

        // ---- vector-atomic scatter: 16 float4 per pair row ----
        const int* idxI = (const int*)(smw + B_IDX);
#pragma unroll
        for (int r = 0; r < 8; r++) {
            int i = tid + r * 256;          // 0..2047
            int row = i >> 4, seg = i & 15;
            int a = idxI[row];
            if (a >= 0) {
                float4 v = *(float4*)&smf[row * 68 + seg * 4];
                red4(g_newp + a * 64 + seg * 4, v.x, v.y, v.z, v.w);
            }
        }
    }
}

// ---------------------------------------------------------------------------
__device__ __forceinline__ void mm4(float acc[4][4], const float* __restrict__ A, int lda,
                                    const float* __restrict__ W, int ldw, int k4) {
    float4 w0 = *(const float4*)(W + (k4 * 4 + 0) * ldw);
    float4 w1 = *(const float4*)(W + (k4 * 4 + 1) * ldw);
    float4 w2 = *(const float4*)(W + (k4 * 4 + 2) * ldw);
    float4 w3 = *(const float4*)(W + (k4 * 4 + 3) * ldw);
#pragma unroll
    for (int i = 0; i < 4; i++) {
        float4 a = *(const float4*)(A + i * lda + k4 * 4);
        acc[i][0] = fmaf(a.x, w0.x, fmaf(a.y, w1.x, fmaf(a.z, w2.x, fmaf(a.w, w3.x, acc[i][0]))));
        acc[i][1] = fmaf(a.x, w0.y, fmaf(a.y, w1.y, fmaf(a.z, w2.y, fmaf(a.w, w3.y, acc[i][1]))));
        acc[i][2] = fmaf(a.x, w0.z, fmaf(a.y, w1.z, fmaf(a.z, w2.z, fmaf(a.w, w3.z, acc[i][2]))));
        acc[i][3] = fmaf(a.x, w0.w, fmaf(a.y, w1.w, fmaf(a.z, w2.w, fmaf(a.w, w3.w, acc[i][3]))));
    }
}

#define PRE_SMEM_BYTES (12416 * 4)
__global__ __launch_bounds__(256, 1) void atom_pre_kernel(
    const float* __restrict__ prop, int d,
    const float* __restrict__ w1, const float* __restrict__ b1,
    const float* __restrict__ w2, const float* __restrict__ b2,
    const float* __restrict__ piw1, const float* __restrict__ pib1)
{
    extern __shared__ float sm[];
    float* sSrc = sm;
    float* sW   = sm + 4096;
    float* sH   = sm + 8192;
    float* sB   = sm + 12288;
    float* sB1  = sm + 12352;

    const int tid = threadIdx.x;
    const int abase = blockIdx.x * 64;
    const int K0 = (d == 0) ? 16 : 64;
    const int kq = K0 >> 2;
    const float* src = (d == 0) ? prop : g_p;

    for (int i = tid; i < K0 * 64; i += 256) sW[i] = w1[i];
    if (tid < 64) { sB[tid] = b1[tid]; sB1[tid] = pib1[tid]; }
    for (int i = tid; i < 64 * kq; i += 256) {
        int a = i / kq, seg = i % kq;
        float4 v = make_float4(0.f, 0.f, 0.f, 0.f);
        if (abase + a < NATOMS) v = ((const float4*)src)[(abase + a) * kq + seg];
        *(float4*)(sSrc + a * 64 + seg * 4) = v;
    }
    for (int i = tid; i < 1024; i += 256) {
        int a = i >> 4;
        if (abase + a < NATOMS)
            ((float4*)g_newp)[(abase + a) * 16 + (i & 15)] = make_float4(0.f, 0.f, 0.f, 0.f);
    }
    __syncthreads();

    const int ar = tid >> 4, cr = tid & 15;
    {
        float acc[4][4];
#pragma unroll
        for (int i = 0; i < 4; i++) { acc[i][0] = acc[i][1] = acc[i][2] = acc[i][3] = 0.f; }
        const float* A = sSrc + ar * 4 * 64;
        const float* W = sW + cr * 4;
        for (int k4 = 0; k4 < kq; k4++) mm4(acc, A, 64, W, 64, k4);
        float4 bv = *(const float4*)(sB + cr * 4);
#pragma unroll
        for (int i = 0; i < 4; i++) {
            float4 v;
            v.x = tfast(acc[i][0] + bv.x); v.y = tfast(acc[i][1] + bv.y);
            v.z = tfast(acc[i][2] + bv.z); v.w = tfast(acc[i][3] + bv.w);
            *(float4*)(sH + (ar * 4 + i) * 64 + cr * 4) = v;
        }
    }
    __syncthreads();
    for (int i = tid; i < 4096; i += 256) sW[i] = w2[i];
    if (tid < 64) sB[tid] = b2[tid];
    __syncthreads();
    {
        float acc[4][4];
#pragma unroll
        for (int i = 0; i < 4; i++) { acc[i][0] = acc[i][1] = acc[i][2] = acc[i][3] = 0.f; }
        const float* A = sH + ar * 4 * 64;
        const float* W = sW + cr * 4;
#pragma unroll 4
        for (int k4 = 0; k4 < 16; k4++) mm4(acc, A, 64, W, 64, k4);
        float4 bv = *(const float4*)(sB + cr * 4);
#pragma unroll
        for (int i = 0; i < 4; i++) {
            int a = abase + ar * 4 + i;
            float4 v;
            v.x = tfast(acc[i][0] + bv.x); v.y = tfast(acc[i][1] + bv.y);
            v.z = tfast(acc[i][2] + bv.z); v.w = tfast(acc[i][3] + bv.w);
            if (a < NATOMS) ((float4*)g_h)[a * 16 + cr] = v;
            *(float4*)(sSrc + (ar * 4 + i) * 64 + cr * 4) = v;
        }
    }
    __syncthreads();

    for (int i = tid; i < 4096; i += 256) sW[i] = piw1[i];
    __syncthreads();
    {
        float acc[4][4];
#pragma unroll
        for (int i = 0; i < 4; i++) { acc[i][0] = acc[i][1] = acc[i][2] = acc[i][3] = 0.f; }
        const float* A = sSrc + ar * 4 * 64;
        const float* W = sW + cr * 4;
#pragma unroll 4
        for (int k4 = 0; k4 < 16; k4++) mm4(acc, A, 64, W, 64, k4);
        float4 bv = *(const float4*)(sB1 + cr * 4);
#pragma unroll
        for (int i = 0; i < 4; i++) {
            int a = abase + ar * 4 + i;
            if (a < NATOMS) {
                float4 v;
                v.x = acc[i][0] + bv.x; v.y = acc[i][1] + bv.y;
                v.z = acc[i][2] + bv.z; v.w = acc[i][3] + bv.w;
                ((float4*)g_u)[a * 16 + cr] = v;
            }
        }
    }
    __syncthreads();

    for (int i = tid; i < 4096; i += 256) sW[i] = piw1[4096 + i];
    __syncthreads();
    {
        float acc[4][4];
#pragma unroll
        for (int i = 0; i < 4; i++) { acc[i][0] = acc[i][1] = acc[i][2] = acc[i][3] = 0.f; }
        const float* A = sSrc + ar * 4 * 64;
        const float* W = sW + cr * 4;
#pragma unroll 4
        for (int k4 = 0; k4 < 16; k4++) mm4(acc, A, 64, W, 64, k4);
#pragma unroll
        for (int i = 0; i < 4; i++) {
            int a = abase + ar * 4 + i;
            if (a < NATOMS) {
                float4 v = make_float4(acc[i][0], acc[i][1], acc[i][2], acc[i][3]);
                ((float4*)g_v)[a * 16 + cr] = v;
            }
        }
    }
}

#define POST_SMEM_BYTES (12928 * 4)
__global__ __launch_bounds__(256, 1) void atom_post_kernel(
    const float* __restrict__ prop, const float* __restrict__ res0w,
    const float* __restrict__ w1, const float* __restrict__ b1,
    const float* __restrict__ w2, const float* __restrict__ b2,
    const float* __restrict__ wo, float* __restrict__ out, int d)
{
    extern __shared__ float sm[];
    float* bufA = sm;
    float* bufB = sm + 4352;
    float* sW   = sm + 8704;
    float* sB   = sm + 12800;
    float* sWo  = sm + 12864;

    const int tid = threadIdx.x;
    const int abase = blockIdx.x * 64;
    const int ar = tid >> 4, cr = tid & 15;

    float pn[4][4];
#pragma unroll
    for (int i = 0; i < 4; i++) { pn[i][0] = pn[i][1] = pn[i][2] = pn[i][3] = 0.f; }

    if (d == 0) {
        for (int i = tid; i < 1024; i += 256) sW[i] = res0w[i];
        for (int i = tid; i < 256; i += 256) {
            int a = i >> 2, seg = i & 3;
            float4 v = make_float4(0.f, 0.f, 0.f, 0.f);
            if (abase + a < NATOMS) v = ((const float4*)prop)[(abase + a) * 4 + seg];
            *(float4*)(bufB + a * 16 + seg * 4) = v;
        }
        __syncthreads();
        const float* A = bufB + ar * 4 * 16;
        const float* W = sW + cr * 4;
#pragma unroll
        for (int k4 = 0; k4 < 4; k4++) mm4(pn, A, 16, W, 64, k4);
    }

#pragma unroll
    for (int i = 0; i < 4; i++) {
        int a = abase + ar * 4 + i;
        float4 v = make_float4(0.f, 0.f, 0.f, 0.f);
        if (a < NATOMS) {
            float4 np = ((const float4*)g_newp)[a * 16 + cr];
            if (d == 0) {
                v.x = pn[i][0] + np.x; v.y = pn[i][1] + np.y;
                v.z = pn[i][2] + np.z; v.w = pn[i][3] + np.w;
            } else {
                float4 pv = ((const float4*)g_p)[a * 16 + cr];
                v.x = pv.x + np.x; v.y = pv.y + np.y;
                v.z = pv.z + np.z; v.w = pv.w + np.w;
            }
            ((float4*)g_p)[a * 16 + cr] = v;
        }
        *(float4*)(bufA + (ar * 4 + i) * 68 + cr * 4) = v;
    }
    __syncthreads();

    for (int i = tid; i < 4096; i += 256) sW[i] = w1[i];
    if (tid < 64) { sB[tid] = b1[tid]; sWo[tid] = wo[tid]; }
    __syncthreads();

    {
        float acc[4][4];
#pragma unroll
        for (int i = 0; i < 4; i++) { acc[i][0] = acc[i][1] = acc[i][2] = acc[i][3] = 0.f; }
        const float* A = bufA + ar * 4 * 68;
        const float* W = sW + cr * 4;
#pragma unroll 4
        for (int k4 = 0; k4 < 16; k4++) mm4(acc, A, 68, W, 64, k4);
        float4 bv = *(const float4*)(sB + cr * 4);
#pragma unroll
        for (int i = 0; i < 4; i++) {
            float4 v;
            v.x = tfast(acc[i][0] + bv.x); v.y = tfast(acc[i][1] + bv.y);
            v.z = tfast(acc[i][2] + bv.z); v.w = tfast(acc[i][3] + bv.w);
            *(float4*)(bufB + (ar * 4 + i) * 68 + cr * 4) = v;
        }
    }
    __syncthreads();
    for (int i = tid; i < 4096; i += 256) sW[i] = w2[i];
    if (tid < 64) sB[tid] = b2[tid];
    __syncthreads();

    {
        float acc[4][4];
#pragma unroll
        for (int i = 0; i < 4; i++) { acc[i][0] = acc[i][1] = acc[i][2] = acc[i][3] = 0.f; }
        const float* A = bufB + ar * 4 * 68;
        const float* W = sW + cr * 4;
#pragma unroll 4
        for (int k4 = 0; k4 < 16; k4++) mm4(acc, A, 68, W, 64, k4);
        float4 bv = *(const float4*)(sB + cr * 4);
#pragma unroll
        for (int i = 0; i < 4; i++) {
            float4 v;
            v.x = tfast(acc[i][0] + bv.x); v.y = tfast(acc[i][1] + bv.y);
            v.z = tfast(acc[i][2] + bv.z); v.w = tfast(acc[i][3] + bv.w);
            *(float4*)(bufA + (ar * 4 + i) * 68 + cr * 4) = v;
        }
    }
    __syncthreads();

    if (tid < 64) {
        int a = abase + tid;
        if (a < NATOMS) {
            float s = 0.f;
            const float* row = bufA + tid * 68;
#pragma unroll 8
            for (int c = 0; c < 64; c++) s = fmaf(row[c], sWo[c], s);
            out[a] = (d == 0) ? s : (out[a] + s);
        }
    }
}

// ---------------------------------------------------------------------------
extern "C" void kernel_launch(void* const* d_in, const int* in_sizes, int n_in,
                              void* d_out, int out_size) {
    const int*   ind2   = (const int*)d_in[0];
    const float* prop   = (const float*)d_in[1];
    const float* basis  = (const float*)d_in[2];
    const float* pp0_w1 = (const float*)d_in[3];
    const float* pp0_b1 = (const float*)d_in[4];
    const float* pp_w1  = (const float*)d_in[5];
    const float* pp_b1  = (const float*)d_in[6];
    const float* pp_w2  = (const float*)d_in[7];
    const float* pp_b2  = (const float*)d_in[8];
    const float* pi_w1  = (const float*)d_in[9];
    const float* pi_b1  = (const float*)d_in[10];
    const float* pi_w2  = (const float*)d_in[11];
    const float* pi_b2  = (const float*)d_in[12];
    const float* ii_w1  = (const float*)d_in[13];
    const float* ii_w2  = (const float*)d_in[14];
    const float* res0   = (const float*)d_in[15];
    const float* ow1    = (const float*)d_in[16];
    const float* ob1    = (const float*)d_in[17];
    const float* ow2    = (const float*)d_in[18];
    const float* ob2    = (const float*)d_in[19];
    const float* owo    = (const float*)d_in[20];
    float* out = (float*)d_out;

    static bool inited = false;
    if (!inited) {
        cudaFuncSetAttribute(pairA, cudaFuncAttributeMaxDynamicSharedMemorySize, A_SMEM_BYTES);
        cudaFuncSetAttribute(pairB, cudaFuncAttributeMaxDynamicSharedMemorySize, B_SMEM_BYTES);
        cudaFuncSetAttribute(atom_pre_kernel, cudaFuncAttributeMaxDynamicSharedMemorySize, PRE_SMEM_BYTES);
        cudaFuncSetAttribute(atom_post_kernel, cudaFuncAttributeMaxDynamicSharedMemorySize, POST_SMEM_BYTES);
        inited = true;
    }

    const int atom_blocks = (NATOMS + 63) / 64;

    for (int d = 0; d < 4; d++) {
        const float* w1 = (d == 0) ? pp0_w1 : pp_w1 + (d - 1) * 4096;
        const float* b1 = (d == 0) ? pp0_b1 : pp_b1 + (d - 1) * 64;
        prep_kernel<<<16, 256>>>(pi_w2 + d * 16384, ii_w1 + d * 4096, ii_w2 + d * 4096);
        atom_pre_kernel<<<atom_blocks, 256, PRE_SMEM_BYTES>>>(
            prop, d, w1, b1, pp_w2 + d * 4096, pp_b2 + d * 64,
            pi_w1 + d * 8192, pi_b1 + d * 64);
        pairA<<<304, 256, A_SMEM_BYTES>>>(ind2, basis, pi_b2 + d * 256);
        pairB<<<456, 256, B_SMEM_BYTES>>>(ind2);
        atom_post_kernel<<<atom_blocks, 256, POST_SMEM_BYTES>>>(
            prop, res0,
            ow1 + d * 4096, ob1 + d * 64,
            ow2 + d * 4096, ob2 + d * 64,
            owo + d * 64, out, d);
    }
}

// round 9
// speedup vs baseline: 3.0271x; 1.0852x over previous
#include <cuda_runtime.h>
#include <cuda_fp16.h>
#include <cstdint>

#define NATOMS 25000
#define NPAIRS 500000
#define NBLKA 7813
#define NBLKB 3907

__device__ __align__(16) float g_h[NATOMS * 64];
__device__ __align__(16) float g_p[NATOMS * 64];
__device__ __align__(16) float g_newp[NATOMS * 64];
__device__ __align__(16) float g_u[NATOMS * 64];
__device__ __align__(16) float g_v[NATOMS * 64];
__device__ __align__(16) uint32_t g_w2H[8192], g_w2L[8192];
__device__ __align__(16) uint32_t g_wi1H[2048], g_wi1L[2048];
__device__ __align__(16) uint32_t g_wi2H[2048], g_wi2L[2048];
__device__ __align__(16) uint32_t g_intH[(NPAIRS + 128) * 32];
__device__ __align__(16) uint32_t g_intL[(NPAIRS + 128) * 32];

__device__ __forceinline__ float tfast(float x) {
    x = fminf(fmaxf(x, -15.f), 15.f);
    float e = __expf(2.f * x);
    return 1.f - __fdividef(2.f, e + 1.f);
}

__device__ __forceinline__ void split2(float x0, float x1, uint32_t& H, uint32_t& L) {
    __half h0 = __float2half_rn(x0), h1 = __float2half_rn(x1);
    float r0 = x0 - __half2float(h0);
    float r1 = x1 - __half2float(h1);
    __half2 hh = __halves2half2(h0, h1);
    __half2 ll = __halves2half2(__float2half_rn(r0), __float2half_rn(r1));
    H = *reinterpret_cast<uint32_t*>(&hh);
    L = *reinterpret_cast<uint32_t*>(&ll);
}

__device__ __forceinline__ void mma16(float* d, uint32_t a0, uint32_t a1, uint32_t a2,
                                      uint32_t a3, uint32_t b0, uint32_t b1) {
    asm volatile("mma.sync.aligned.m16n8k16.row.col.f32.f16.f16.f32 "
        "{%0,%1,%2,%3}, {%4,%5,%6,%7}, {%8,%9}, {%0,%1,%2,%3};"
        : "+f"(d[0]), "+f"(d[1]), "+f"(d[2]), "+f"(d[3])
        : "r"(a0), "r"(a1), "r"(a2), "r"(a3), "r"(b0), "r"(b1));
}

__device__ __forceinline__ void red4(float* p, float a, float b, float c, float d) {
    asm volatile("red.global.add.v4.f32 [%0], {%1,%2,%3,%4};"
        :: "l"(p), "f"(a), "f"(b), "f"(c), "f"(d) : "memory");
}

// 3-term fp16 warp GEMM: 32 rows x 32 cols, K=16*KC.
// WH/WL may point to shared OR global fragment arrays (same layout).
template<int KC>
__device__ __forceinline__ void gemm16(const uint32_t* __restrict__ AH, const uint32_t* __restrict__ AL,
        const uint32_t* __restrict__ WH, const uint32_t* __restrict__ WL,
        int r0, int tileBase, int lane, float acc[2][4][4])
{
    const int tig = lane & 3, gid = lane >> 2;
    const int sw = gid << 2;
#pragma unroll
    for (int kc = 0; kc < KC; kc++) {
        int k0 = (kc * 8 + tig) ^ sw;
        int k1 = (kc * 8 + tig + 4) ^ sw;
        uint32_t ah[2][4], al[2][4];
#pragma unroll
        for (int mt = 0; mt < 2; mt++) {
            const uint32_t* bh = AH + (r0 + mt * 16 + gid) * 32;
            const uint32_t* bl = AL + (r0 + mt * 16 + gid) * 32;
            ah[mt][0] = bh[k0]; ah[mt][1] = bh[256 + k0];
            ah[mt][2] = bh[k1]; ah[mt][3] = bh[256 + k1];
            al[mt][0] = bl[k0]; al[mt][1] = bl[256 + k0];
            al[mt][2] = bl[k1]; al[mt][3] = bl[256 + k1];
        }
#pragma unroll
        for (int nt = 0; nt < 4; nt++) {
            int wi = ((tileBase + nt) * KC + kc) * 64 + lane * 2;
            uint2 bh = *(const uint2*)(WH + wi);
            uint2 bl = *(const uint2*)(WL + wi);
#pragma unroll
            for (int mt = 0; mt < 2; mt++) {
                mma16(acc[mt][nt], ah[mt][0], ah[mt][1], ah[mt][2], ah[mt][3], bh.x, bh.y);
                mma16(acc[mt][nt], ah[mt][0], ah[mt][1], ah[mt][2], ah[mt][3], bl.x, bl.y);
                mma16(acc[mt][nt], al[mt][0], al[mt][1], al[mt][2], al[mt][3], bh.x, bh.y);
            }
        }
    }
}

// ---------------------------------------------------------------------------
__global__ void prep_kernel(const float* __restrict__ w2,
                            const float* __restrict__ wi1, const float* __restrict__ wi2) {
    int tid = blockIdx.x * blockDim.x + threadIdx.x;
    int stride = gridDim.x * blockDim.x;
    for (int idx = tid; idx < 4096; idx += stride) {
        int lane = idx & 31, kc = (idx >> 5) & 3, t = idx >> 7;
        int n = t * 8 + (lane >> 2);
        int k0 = kc * 16 + 2 * (lane & 3);
        int o = (t * 4 + kc) * 64 + lane * 2;
        uint32_t h, l;
        split2(w2[k0 * 256 + n], w2[(k0 + 1) * 256 + n], h, l);
        g_w2H[o] = h; g_w2L[o] = l;
        split2(w2[(k0 + 8) * 256 + n], w2[(k0 + 9) * 256 + n], h, l);
        g_w2H[o + 1] = h; g_w2L[o + 1] = l;
    }
    for (int idx = tid; idx < 1024; idx += stride) {
        int lane = idx & 31, kc = (idx >> 5) & 3, t = idx >> 7;
        int n = t * 8 + (lane >> 2);
        int k0 = kc * 16 + 2 * (lane & 3);
        int o = (t * 4 + kc) * 64 + lane * 2;
        uint32_t h, l;
        split2(wi1[k0 * 64 + n], wi1[(k0 + 1) * 64 + n], h, l);
        g_wi1H[o] = h; g_wi1L[o] = l;
        split2(wi1[(k0 + 8) * 64 + n], wi1[(k0 + 9) * 64 + n], h, l);
        g_wi1H[o + 1] = h; g_wi1L[o + 1] = l;
        split2(wi2[k0 * 64 + n], wi2[(k0 + 1) * 64 + n], h, l);
        g_wi2H[o] = h; g_wi2L[o] = l;
        split2(wi2[(k0 + 8) * 64 + n], wi2[(k0 + 9) * 64 + n], h, l);
        g_wi2H[o + 1] = h; g_wi2L[o + 1] = l;
    }
    for (int i = tid; i < 4096; i += stride) {
        g_intH[NPAIRS * 32 + i] = 0;
        g_intL[NPAIRS * 32 + i] = 0;
    }
}

// ---------------------------------------------------------------------------
// pairA: persistent, 64 pairs/iter, 3 CTAs/SM. W2 hi in smem, W2 lo streamed
// from global (L1-resident, warp-uniform). gather+tanh -> stage2 -> g_int.
// ---------------------------------------------------------------------------
#define A_W2H  0        // 8192 words (32KB)
#define A_WW1H 8192     // 2048
#define A_WW1L 10240    // 2048
#define A_INTH 12288    // 2048
#define A_INTL 14336    // 2048
#define A_BAS  16384    // 256 floats
#define A_B2   16640    // 256 floats
#define A_SMEM_BYTES (16896 * 4)

__global__ __launch_bounds__(256, 3) void pairA(
    const int* __restrict__ ind2, const float* __restrict__ basis,
    const float* __restrict__ b2)
{
    extern __shared__ uint32_t smw[];
    float* smf = (float*)smw;
    const int tid = threadIdx.x;

    for (int i = tid; i < 2048; i += 256) ((uint4*)(smw + A_W2H))[i] = ((const uint4*)g_w2H)[i];
    if (tid < 128) { smf[A_B2 + tid] = b2[tid]; smf[A_B2 + 128 + tid] = b2[128 + tid]; }

    const int lane = tid & 31, w = tid >> 5;
    const int rg = w & 1, cg = w >> 1;       // 2 row-groups x 4 col-groups
    const int r0 = rg * 32;
    const int tig = lane & 3, gid = lane >> 2;

    for (int blk = blockIdx.x; blk < NBLKA; blk += gridDim.x) {
        const int pairbase = blk * 64;
        __syncthreads();   // prior iteration's reads of WW1/BAS/INT done

        if (tid < 64) {
            int p = pairbase + tid;
            float4 bs = make_float4(0.f, 0.f, 0.f, 0.f);
            if (p < NPAIRS) bs = ((const float4*)basis)[p];
            ((float4*)(smf + A_BAS))[tid] = bs;
        }
        // stage 1: ww1 = tanh(u[i] + v[j]) -> packed hi/lo
#pragma unroll
        for (int r = 0; r < 8; r++) {
            int idx = tid + r * 256;
            int row = idx >> 5, kp = idx & 31;
            int gp = pairbase + row;
            float x0 = 0.f, x1 = 0.f;
            if (gp < NPAIRS) {
                int ai = ind2[2 * gp], aj = ind2[2 * gp + 1];
                float2 u = *(const float2*)&g_u[ai * 64 + 2 * kp];
                float2 v = *(const float2*)&g_v[aj * 64 + 2 * kp];
                x0 = tfast(u.x + v.x);
                x1 = tfast(u.y + v.y);
            }
            uint32_t H, L; split2(x0, x1, H, L);
            int o = row * 32 + (kp ^ ((row & 7) << 2));
            smw[A_WW1H + o] = H; smw[A_WW1L + o] = L;
        }
        __syncthreads();

        float4 bsv[4];
#pragma unroll
        for (int q = 0; q < 4; q++) bsv[q] = ((float4*)(smf + A_BAS))[r0 + gid + q * 8];
#pragma unroll 1
        for (int j = 0; j < 2; j++) {
            int g = cg + 4 * j;
            float acc[2][4][4];
#pragma unroll
            for (int a = 0; a < 2; a++)
#pragma unroll
                for (int b = 0; b < 4; b++)
#pragma unroll
                    for (int q = 0; q < 4; q++) acc[a][b][q] = 0.f;
            gemm16<4>(smw + A_WW1H, smw + A_WW1L, smw + A_W2H, g_w2L, r0, g * 4, lane, acc);
#pragma unroll
            for (int mt = 0; mt < 2; mt++)
#pragma unroll
                for (int nt = 0; nt < 4; nt++) {
                    int c0 = g * 32 + nt * 8 + 2 * tig;
                    float b20 = smf[A_B2 + c0], b21 = smf[A_B2 + c0 + 1];
                    float4 bL = bsv[mt * 2], bH = bsv[mt * 2 + 1];
                    float cL0 = (tig & 1) ? bL.z : bL.x, cL1 = (tig & 1) ? bL.w : bL.y;
                    float cH0 = (tig & 1) ? bH.z : bH.x, cH1 = (tig & 1) ? bH.w : bH.y;
                    float pl = tfast(acc[mt][nt][0] + b20) * cL0 + tfast(acc[mt][nt][1] + b21) * cL1;
                    float ph = tfast(acc[mt][nt][2] + b20) * cH0 + tfast(acc[mt][nt][3] + b21) * cH1;
                    pl += __shfl_xor_sync(0xffffffffu, pl, 1);
                    ph += __shfl_xor_sync(0xffffffffu, ph, 1);
                    float pl2 = __shfl_xor_sync(0xffffffffu, pl, 2);
                    float ph2 = __shfl_xor_sync(0xffffffffu, ph, 2);
                    if (tig == 0) {
                        int kp = g * 4 + nt;
                        int rL = r0 + mt * 16 + gid, rH = rL + 8;
                        uint32_t H, L;
                        split2(pl, pl2, H, L);
                        int o = rL * 32 + (kp ^ (gid << 2));
                        smw[A_INTH + o] = H; smw[A_INTL + o] = L;
                        split2(ph, ph2, H, L);
                        o = rH * 32 + (kp ^ (gid << 2));
                        smw[A_INTH + o] = H; smw[A_INTL + o] = L;
                    }
                }
        }
        __syncthreads();
        for (int i = tid; i < 512; i += 256) {
            ((uint4*)(g_intH + pairbase * 32))[i] = ((uint4*)(smw + A_INTH))[i];
            ((uint4*)(g_intL + pairbase * 32))[i] = ((uint4*)(smw + A_INTL))[i];
        }
    }
}

// ---------------------------------------------------------------------------
// pairB: persistent, 128 pairs/iter, 3 CTAs/SM. inter -> t1 -> t2 -> red.v4.
// ---------------------------------------------------------------------------
#define B_R0   0
#define B_WI1H 8704
#define B_WI1L 10752
#define B_WI2H 12800
#define B_WI2L 14848
#define B_IDX  16896
#define B_SMEM_BYTES (17024 * 4)

__global__ __launch_bounds__(256, 3) void pairB(const int* __restrict__ ind2)
{
    extern __shared__ uint32_t smw[];
    float* smf = (float*)smw;
    const int tid = threadIdx.x;

    for (int i = tid; i < 512; i += 256) {
        ((uint4*)(smw + B_WI1H))[i] = ((const uint4*)g_wi1H)[i];
        ((uint4*)(smw + B_WI1L))[i] = ((const uint4*)g_wi1L)[i];
        ((uint4*)(smw + B_WI2H))[i] = ((const uint4*)g_wi2H)[i];
        ((uint4*)(smw + B_WI2L))[i] = ((const uint4*)g_wi2L)[i];
    }

    const int lane = tid & 31, w = tid >> 5;
    const int rg = w & 3, cg = w >> 2;       // 4 row-groups x 2 col-groups
    const int r0 = rg * 32;
    const int tig = lane & 3, gid = lane >> 2;

    for (int blk = blockIdx.x; blk < NBLKB; blk += gridDim.x) {
        const int pairbase = blk * 128;
        __syncthreads();

        for (int i = tid; i < 1024; i += 256) {
            ((uint4*)(smw + B_R0))[i] = ((const uint4*)(g_intH + pairbase * 32))[i];
            ((uint4*)(smw + B_R0 + 4096))[i] = ((const uint4*)(g_intL + pairbase * 32))[i];
        }
        if (tid < 128) {
            int p = pairbase + tid;
            ((int*)(smw + B_IDX))[tid] = (p < NPAIRS) ? ind2[2 * p] : -1;
        }
        __syncthreads();

        // ---- stage 3: t1 = tanh(inter @ ii_w1) ----
        float acc[2][4][4];
#pragma unroll
        for (int a = 0; a < 2; a++)
#pragma unroll
            for (int b = 0; b < 4; b++)
#pragma unroll
                for (int q = 0; q < 4; q++) acc[a][b][q] = 0.f;
        gemm16<4>(smw + B_R0, smw + B_R0 + 4096, smw + B_WI1H, smw + B_WI1L, r0, cg * 4, lane, acc);
        __syncthreads();
#pragma unroll
        for (int mt = 0; mt < 2; mt++)
#pragma unroll
            for (int nt = 0; nt < 4; nt++) {
                int kp = cg * 16 + nt * 4 + tig;
                int rL = r0 + mt * 16 + gid, rH = rL + 8;
                uint32_t H, L;
                split2(tfast(acc[mt][nt][0]), tfast(acc[mt][nt][1]), H, L);
                int o = rL * 32 + (kp ^ (gid << 2));
                smw[B_R0 + o] = H; smw[B_R0 + 4096 + o] = L;
                split2(tfast(acc[mt][nt][2]), tfast(acc[mt][nt][3]), H, L);
                o = rH * 32 + (kp ^ (gid << 2));
                smw[B_R0 + o] = H; smw[B_R0 + 4096 + o] = L;
            }
        __syncthreads();

        // ---- stage 4: t2 = tanh(t1 @ ii_w2) ----
#pragma unroll
        for (int a = 0; a < 2; a++)
#pragma unroll
            for (int b = 0; b < 4; b++)
#pragma unroll
                for (int q = 0; q < 4; q++) acc[a][b][q] = 0.f;
        gemm16<4>(smw + B_R0, smw + B_R0 + 4096, smw + B_WI2H, smw + B_WI2L, r0, cg * 4, lane, acc);
        __syncthreads();
#pragma unroll
        for (int mt = 0; mt < 2; mt++)
#pragma unroll
            for (int nt = 0; nt < 4; nt++) {
                int c0 = cg * 32 + nt * 8 + 2 * tig;
                int rL = r0 + mt * 16 + gid, rH = rL + 8;
                float2 v;
                v.x = tfast(acc[mt][nt][0]); v.y = tfast(acc[mt][nt][1]);
                *(float2*)&smf[rL * 68 + c0] = v;
                v.x = tfast(acc[mt][nt][2]); v.y = tfast(acc[mt][nt][3]);
                *(float2*)&smf[rH * 68 + c0] = v;
            }
        __syncthreads();

        const int* idxI = (const int*)(smw + B_IDX);
#pragma unroll
        for (int r = 0; r < 8; r++) {
            int i = tid + r * 256;
            int row = i >> 4, seg = i & 15;
            int a = idxI[row];
            if (a >= 0) {
                float4 v = *(float4*)&smf[row * 68 + seg * 4];
                red4(g_newp + a * 64 + seg * 4, v.x, v.y, v.z, v.w);
            }
        }
    }
}

// ---------------------------------------------------------------------------
__device__ __forceinline__ void mm4(float acc[4][4], const float* __restrict__ A, int lda,
                                    const float* __restrict__ W, int ldw, int k4) {
    float4 w0 = *(const float4*)(W + (k4 * 4 + 0) * ldw);
    float4 w1 = *(const float4*)(W + (k4 * 4 + 1) * ldw);
    float4 w2 = *(const float4*)(W + (k4 * 4 + 2) * ldw);
    float4 w3 = *(const float4*)(W + (k4 * 4 + 3) * ldw);
#pragma unroll
    for (int i = 0; i < 4; i++) {
        float4 a = *(const float4*)(A + i * lda + k4 * 4);
        acc[i][0] = fmaf(a.x, w0.x, fmaf(a.y, w1.x, fmaf(a.z, w2.x, fmaf(a.w, w3.x, acc[i][0]))));
        acc[i][1] = fmaf(a.x, w0.y, fmaf(a.y, w1.y, fmaf(a.z, w2.y, fmaf(a.w, w3.y, acc[i][1]))));
        acc[i][2] = fmaf(a.x, w0.z, fmaf(a.y, w1.z, fmaf(a.z, w2.z, fmaf(a.w, w3.z, acc[i][2]))));
        acc[i][3] = fmaf(a.x, w0.w, fmaf(a.y, w1.w, fmaf(a.z, w2.w, fmaf(a.w, w3.w, acc[i][3]))));
    }
}

#define PRE_SMEM_BYTES (12416 * 4)
__global__ __launch_bounds__(256, 1) void atom_pre_kernel(
    const float* __restrict__ prop, int d,
    const float* __restrict__ w1, const float* __restrict__ b1,
    const float* __restrict__ w2, const float* __restrict__ b2,
    const float* __restrict__ piw1, const float* __restrict__ pib1)
{
    extern __shared__ float sm[];
    float* sSrc = sm;
    float* sW   = sm + 4096;
    float* sH   = sm + 8192;
    float* sB   = sm + 12288;
    float* sB1  = sm + 12352;

    const int tid = threadIdx.x;
    const int abase = blockIdx.x * 64;
    const int K0 = (d == 0) ? 16 : 64;
    const int kq = K0 >> 2;
    const float* src = (d == 0) ? prop : g_p;

    for (int i = tid; i < K0 * 64; i += 256) sW[i] = w1[i];
    if (tid < 64) { sB[tid] = b1[tid]; sB1[tid] = pib1[tid]; }
    for (int i = tid; i < 64 * kq; i += 256) {
        int a = i / kq, seg = i % kq;
        float4 v = make_float4(0.f, 0.f, 0.f, 0.f);
        if (abase + a < NATOMS) v = ((const float4*)src)[(abase + a) * kq + seg];
        *(float4*)(sSrc + a * 64 + seg * 4) = v;
    }
    for (int i = tid; i < 1024; i += 256) {
        int a = i >> 4;
        if (abase + a < NATOMS)
            ((float4*)g_newp)[(abase + a) * 16 + (i & 15)] = make_float4(0.f, 0.f, 0.f, 0.f);
    }
    __syncthreads();

    const int ar = tid >> 4, cr = tid & 15;
    {
        float acc[4][4];
#pragma unroll
        for (int i = 0; i < 4; i++) { acc[i][0] = acc[i][1] = acc[i][2] = acc[i][3] = 0.f; }
        const float* A = sSrc + ar * 4 * 64;
        const float* W = sW + cr * 4;
        for (int k4 = 0; k4 < kq; k4++) mm4(acc, A, 64, W, 64, k4);
        float4 bv = *(const float4*)(sB + cr * 4);
#pragma unroll
        for (int i = 0; i < 4; i++) {
            float4 v;
            v.x = tfast(acc[i][0] + bv.x); v.y = tfast(acc[i][1] + bv.y);
            v.z = tfast(acc[i][2] + bv.z); v.w = tfast(acc[i][3] + bv.w);
            *(float4*)(sH + (ar * 4 + i) * 64 + cr * 4) = v;
        }
    }
    __syncthreads();
    for (int i = tid; i < 4096; i += 256) sW[i] = w2[i];
    if (tid < 64) sB[tid] = b2[tid];
    __syncthreads();
    {
        float acc[4][4];
#pragma unroll
        for (int i = 0; i < 4; i++) { acc[i][0] = acc[i][1] = acc[i][2] = acc[i][3] = 0.f; }
        const float* A = sH + ar * 4 * 64;
        const float* W = sW + cr * 4;
#pragma unroll 4
        for (int k4 = 0; k4 < 16; k4++) mm4(acc, A, 64, W, 64, k4);
        float4 bv = *(const float4*)(sB + cr * 4);
#pragma unroll
        for (int i = 0; i < 4; i++) {
            int a = abase + ar * 4 + i;
            float4 v;
            v.x = tfast(acc[i][0] + bv.x); v.y = tfast(acc[i][1] + bv.y);
            v.z = tfast(acc[i][2] + bv.z); v.w = tfast(acc[i][3] + bv.w);
            if (a < NATOMS) ((float4*)g_h)[a * 16 + cr] = v;
            *(float4*)(sSrc + (ar * 4 + i) * 64 + cr * 4) = v;
        }
    }
    __syncthreads();

    for (int i = tid; i < 4096; i += 256) sW[i] = piw1[i];
    __syncthreads();
    {
        float acc[4][4];
#pragma unroll
        for (int i = 0; i < 4; i++) { acc[i][0] = acc[i][1] = acc[i][2] = acc[i][3] = 0.f; }
        const float* A = sSrc + ar * 4 * 64;
        const float* W = sW + cr * 4;
#pragma unroll 4
        for (int k4 = 0; k4 < 16; k4++) mm4(acc, A, 64, W, 64, k4);
        float4 bv = *(const float4*)(sB1 + cr * 4);
#pragma unroll
        for (int i = 0; i < 4; i++) {
            int a = abase + ar * 4 + i;
            if (a < NATOMS) {
                float4 v;
                v.x = acc[i][0] + bv.x; v.y = acc[i][1] + bv.y;
                v.z = acc[i][2] + bv.z; v.w = acc[i][3] + bv.w;
                ((float4*)g_u)[a * 16 + cr] = v;
            }
        }
    }
    __syncthreads();

    for (int i = tid; i < 4096; i += 256) sW[i] = piw1[4096 + i];
    __syncthreads();
    {
        float acc[4][4];
#pragma unroll
        for (int i = 0; i < 4; i++) { acc[i][0] = acc[i][1] = acc[i][2] = acc[i][3] = 0.f; }
        const float* A = sSrc + ar * 4 * 64;
        const float* W = sW + cr * 4;
#pragma unroll 4
        for (int k4 = 0; k4 < 16; k4++) mm4(acc, A, 64, W, 64, k4);
#pragma unroll
        for (int i = 0; i < 4; i++) {
            int a = abase + ar * 4 + i;
            if (a < NATOMS) {
                float4 v = make_float4(acc[i][0], acc[i][1], acc[i][2], acc[i][3]);
                ((float4*)g_v)[a * 16 + cr] = v;
            }
        }
    }
}

#define POST_SMEM_BYTES (12928 * 4)
__global__ __launch_bounds__(256, 1) void atom_post_kernel(
    const float* __restrict__ prop, const float* __restrict__ res0w,
    const float* __restrict__ w1, const float* __restrict__ b1,
    const float* __restrict__ w2, const float* __restrict__ b2,
    const float* __restrict__ wo, float* __restrict__ out, int d)
{
    extern __shared__ float sm[];
    float* bufA = sm;
    float* bufB = sm + 4352;
    float* sW   = sm + 8704;
    float* sB   = sm + 12800;
    float* sWo  = sm + 12864;

    const int tid = threadIdx.x;
    const int abase = blockIdx.x * 64;
    const int ar = tid >> 4, cr = tid & 15;

    float pn[4][4];
#pragma unroll
    for (int i = 0; i < 4; i++) { pn[i][0] = pn[i][1] = pn[i][2] = pn[i][3] = 0.f; }

    if (d == 0) {
        for (int i = tid; i < 1024; i += 256) sW[i] = res0w[i];
        for (int i = tid; i < 256; i += 256) {
            int a = i >> 2, seg = i & 3;
            float4 v = make_float4(0.f, 0.f, 0.f, 0.f);
            if (abase + a < NATOMS) v = ((const float4*)prop)[(abase + a) * 4 + seg];
            *(float4*)(bufB + a * 16 + seg * 4) = v;
        }
        __syncthreads();
        const float* A = bufB + ar * 4 * 16;
        const float* W = sW + cr * 4;
#pragma unroll
        for (int k4 = 0; k4 < 4; k4++) mm4(pn, A, 16, W, 64, k4);
    }

#pragma unroll
    for (int i = 0; i < 4; i++) {
        int a = abase + ar * 4 + i;
        float4 v = make_float4(0.f, 0.f, 0.f, 0.f);
        if (a < NATOMS) {
            float4 np = ((const float4*)g_newp)[a * 16 + cr];
            if (d == 0) {
                v.x = pn[i][0] + np.x; v.y = pn[i][1] + np.y;
                v.z = pn[i][2] + np.z; v.w = pn[i][3] + np.w;
            } else {
                float4 pv = ((const float4*)g_p)[a * 16 + cr];
                v.x = pv.x + np.x; v.y = pv.y + np.y;
                v.z = pv.z + np.z; v.w = pv.w + np.w;
            }
            ((float4*)g_p)[a * 16 + cr] = v;
        }
        *(float4*)(bufA + (ar * 4 + i) * 68 + cr * 4) = v;
    }
    __syncthreads();

    for (int i = tid; i < 4096; i += 256) sW[i] = w1[i];
    if (tid < 64) { sB[tid] = b1[tid]; sWo[tid] = wo[tid]; }
    __syncthreads();

    {
        float acc[4][4];
#pragma unroll
        for (int i = 0; i < 4; i++) { acc[i][0] = acc[i][1] = acc[i][2] = acc[i][3] = 0.f; }
        const float* A = bufA + ar * 4 * 68;
        const float* W = sW + cr * 4;
#pragma unroll 4
        for (int k4 = 0; k4 < 16; k4++) mm4(acc, A, 68, W, 64, k4);
        float4 bv = *(const float4*)(sB + cr * 4);
#pragma unroll
        for (int i = 0; i < 4; i++) {
            float4 v;
            v.x = tfast(acc[i][0] + bv.x); v.y = tfast(acc[i][1] + bv.y);
            v.z = tfast(acc[i][2] + bv.z); v.w = tfast(acc[i][3] + bv.w);
            *(float4*)(bufB + (ar * 4 + i) * 68 + cr * 4) = v;
        }
    }
    __syncthreads();
    for (int i = tid; i < 4096; i += 256) sW[i] = w2[i];
    if (tid < 64) sB[tid] = b2[tid];
    __syncthreads();

    {
        float acc[4][4];
#pragma unroll
        for (int i = 0; i < 4; i++) { acc[i][0] = acc[i][1] = acc[i][2] = acc[i][3] = 0.f; }
        const float* A = bufB + ar * 4 * 68;
        const float* W = sW + cr * 4;
#pragma unroll 4
        for (int k4 = 0; k4 < 16; k4++) mm4(acc, A, 68, W, 64, k4);
        float4 bv = *(const float4*)(sB + cr * 4);
#pragma unroll
        for (int i = 0; i < 4; i++) {
            float4 v;
            v.x = tfast(acc[i][0] + bv.x); v.y = tfast(acc[i][1] + bv.y);
            v.z = tfast(acc[i][2] + bv.z); v.w = tfast(acc[i][3] + bv.w);
            *(float4*)(bufA + (ar * 4 + i) * 68 + cr * 4) = v;
        }
    }
    __syncthreads();

    if (tid < 64) {
        int a = abase + tid;
        if (a < NATOMS) {
            float s = 0.f;
            const float* row = bufA + tid * 68;
#pragma unroll 8
            for (int c = 0; c < 64; c++) s = fmaf(row[c], sWo[c], s);
            out[a] = (d == 0) ? s : (out[a] + s);
        }
    }
}

// ---------------------------------------------------------------------------
extern "C" void kernel_launch(void* const* d_in, const int* in_sizes, int n_in,
                              void* d_out, int out_size) {
    const int*   ind2   = (const int*)d_in[0];
    const float* prop   = (const float*)d_in[1];
    const float* basis  = (const float*)d_in[2];
    const float* pp0_w1 = (const float*)d_in[3];
    const float* pp0_b1 = (const float*)d_in[4];
    const float* pp_w1  = (const float*)d_in[5];
    const float* pp_b1  = (const float*)d_in[6];
    const float* pp_w2  = (const float*)d_in[7];
    const float* pp_b2  = (const float*)d_in[8];
    const float* pi_w1  = (const float*)d_in[9];
    const float* pi_b1  = (const float*)d_in[10];
    const float* pi_w2  = (const float*)d_in[11];
    const float* pi_b2  = (const float*)d_in[12];
    const float* ii_w1  = (const float*)d_in[13];
    const float* ii_w2  = (const float*)d_in[14];
    const float* res0   = (const float*)d_in[15];
    const float* ow1    = (const float*)d_in[16];
    const float* ob1    = (const float*)d_in[17];
    const float* ow2    = (const float*)d_in[18];
    const float* ob2    = (const float*)d_in[19];
    const float* owo    = (const float*)d_in[20];
    float* out = (float*)d_out;

    static bool inited = false;
    if (!inited) {
        cudaFuncSetAttribute(pairA, cudaFuncAttributeMaxDynamicSharedMemorySize, A_SMEM_BYTES);
        cudaFuncSetAttribute(pairB, cudaFuncAttributeMaxDynamicSharedMemorySize, B_SMEM_BYTES);
        cudaFuncSetAttribute(atom_pre_kernel, cudaFuncAttributeMaxDynamicSharedMemorySize, PRE_SMEM_BYTES);
        cudaFuncSetAttribute(atom_post_kernel, cudaFuncAttributeMaxDynamicSharedMemorySize, POST_SMEM_BYTES);
        inited = true;
    }

    const int atom_blocks = (NATOMS + 63) / 64;

    for (int d = 0; d < 4; d++) {
        const float* w1 = (d == 0) ? pp0_w1 : pp_w1 + (d - 1) * 4096;
        const float* b1 = (d == 0) ? pp0_b1 : pp_b1 + (d - 1) * 64;
        prep_kernel<<<16, 256>>>(pi_w2 + d * 16384, ii_w1 + d * 4096, ii_w2 + d * 4096);
        atom_pre_kernel<<<atom_blocks, 256, PRE_SMEM_BYTES>>>(
            prop, d, w1, b1, pp_w2 + d * 4096, pp_b2 + d * 64,
            pi_w1 + d * 8192, pi_b1 + d * 64);
        pairA<<<456, 256, A_SMEM_BYTES>>>(ind2, basis, pi_b2 + d * 256);
        pairB<<<456, 256, B_SMEM_BYTES>>>(ind2);
        atom_post_kernel<<<atom_blocks, 256, POST_SMEM_BYTES>>>(
            prop, res0,
            ow1 + d * 4096, ob1 + d * 64,
            ow2 + d * 4096, ob2 + d * 64,
            owo + d * 64, out, d);
    }
}